// round 1
// baseline (speedup 1.0000x reference)
#include <cuda_runtime.h>
#include <cuda_bf16.h>

// Problem constants
#define Bb 16
#define Ss 2048
#define Dd 1024
#define Vv 128          // vocab
#define Ll 4
#define NB (Dd/2)       // rotation blocks = 512
#define ROWS (Bb*Ss)    // 32768

// ---------------- scratch (device globals; no allocation allowed) ----------
__device__ float g_a [ROWS*Dd];   // activations (residual stream)
__device__ float g_xn[ROWS*Dd];   // layernorm output
__device__ float g_u [ROWS*Dd];   // x@Wx ; later overwritten in-place by h*v ; also t1
__device__ float g_v [ROWS*Dd];   // x@Wv

// ---------------- embedding gather ----------------
__global__ __launch_bounds__(256) void embed_kernel(const int* __restrict__ idx,
                                                    const float* __restrict__ emb,
                                                    float* __restrict__ a) {
    int i = blockIdx.x * 256 + threadIdx.x;        // over ROWS * (D/4)
    int row = i >> 8;                               // D/4 = 256
    int col = i & 255;
    int tok = idx[row];
    ((float4*)a)[i] = ((const float4*)emb)[tok * 256 + col];
}

// ---------------- layernorm: one block per row ----------------
__global__ __launch_bounds__(256) void ln_kernel(const float* __restrict__ x,
                                                 const float* __restrict__ gamma,
                                                 const float* __restrict__ beta,
                                                 float* __restrict__ y) {
    __shared__ float red_s[8];
    __shared__ float red_q[8];
    int row = blockIdx.x;
    int t = threadIdx.x;
    float4 v = ((const float4*)(x + (size_t)row * Dd))[t];
    float s  = v.x + v.y + v.z + v.w;
    float ss = v.x*v.x + v.y*v.y + v.z*v.z + v.w*v.w;
    // warp reduce
    #pragma unroll
    for (int o = 16; o > 0; o >>= 1) {
        s  += __shfl_xor_sync(0xffffffff, s,  o);
        ss += __shfl_xor_sync(0xffffffff, ss, o);
    }
    if ((t & 31) == 0) { red_s[t >> 5] = s; red_q[t >> 5] = ss; }
    __syncthreads();
    if (t < 8) { s = red_s[t]; ss = red_q[t]; }
    if (t < 32) {
        #pragma unroll
        for (int o = 4; o > 0; o >>= 1) {
            s  += __shfl_xor_sync(0xffffffff, s,  o);
            ss += __shfl_xor_sync(0xffffffff, ss, o);
        }
        if (t == 0) { red_s[0] = s; red_q[0] = ss; }
    }
    __syncthreads();
    float mu  = red_s[0] * (1.0f / Dd);
    float var = red_q[0] * (1.0f / Dd) - mu * mu;
    float inv = rsqrtf(var + 1e-5f);
    float4 g4 = ((const float4*)gamma)[t];
    float4 b4 = ((const float4*)beta)[t];
    float4 o;
    o.x = (v.x - mu) * inv * g4.x + b4.x;
    o.y = (v.y - mu) * inv * g4.y + b4.y;
    o.z = (v.z - mu) * inv * g4.z + b4.z;
    o.w = (v.w - mu) * inv * g4.w + b4.w;
    ((float4*)(y + (size_t)row * Dd))[t] = o;
}

// ---------------- linear-RNN scan over 2x2 rotation blocks ----------------
// h_t = R(theta) h_{t-1} + u_t ; writes g = h * v IN PLACE into u.
__global__ __launch_bounds__(256) void scan_kernel(float* __restrict__ u,
                                                   const float* __restrict__ v,
                                                   const float* __restrict__ theta) {
    int tid = blockIdx.x * 256 + threadIdx.x;   // 0 .. B*NB-1 = 8191
    int b   = tid / NB;
    int blk = tid % NB;
    float th = theta[blk];
    float c = cosf(th), sn = sinf(th);
    float hx = 0.f, hy = 0.f;
    size_t base = (size_t)b * Ss * (Dd / 2) + blk;   // in float2 units
    float2*       up = (float2*)u + base;
    const float2* vp = (const float2*)v + base;
    for (int s0 = 0; s0 < Ss; s0 += 8) {
        float2 ub[8], vb[8];
        #pragma unroll
        for (int j = 0; j < 8; j++) {
            ub[j] = up[(size_t)(s0 + j) * (Dd / 2)];
            vb[j] = vp[(size_t)(s0 + j) * (Dd / 2)];
        }
        #pragma unroll
        for (int j = 0; j < 8; j++) {
            float nx = c * hx - sn * hy + ub[j].x;
            float ny = sn * hx + c  * hy + ub[j].y;
            hx = nx; hy = ny;
            up[(size_t)(s0 + j) * (Dd / 2)] = make_float2(hx * vb[j].x, hy * vb[j].y);
        }
    }
}

// ---------------- fp32 SGEMM, 128x128x16 tile, 8x8/thread ----------------
// C = A[M,K] @ Bm[K,N] + bias[N] (+ Cin if flags&1) (relu if flags&2)
#define GBM 128
#define GBN 128
#define GBK 16
__global__ __launch_bounds__(256) void gemm_kernel(const float* __restrict__ A,
                                                   const float* __restrict__ Bm,
                                                   const float* __restrict__ bias,
                                                   const float* __restrict__ Cin,
                                                   float* __restrict__ C,
                                                   int Mdim, int Ndim, int Kdim,
                                                   int flags) {
    __shared__ __align__(16) float As[GBK][GBM];
    __shared__ __align__(16) float Bs[GBK][GBN];
    int bx = blockIdx.x;           // N tile
    int by = blockIdx.y;           // M tile
    int tid = threadIdx.x;
    int tx = tid & 15;             // 0..15 -> 8 cols each
    int ty = tid >> 4;             // 0..15 -> 8 rows each

    const float* Aptr = A  + (size_t)by * GBM * Kdim;
    const float* Bptr = Bm + (size_t)bx * GBN;

    float acc[8][8];
    #pragma unroll
    for (int i = 0; i < 8; i++)
        #pragma unroll
        for (int j = 0; j < 8; j++) acc[i][j] = 0.f;

    for (int k0 = 0; k0 < Kdim; k0 += GBK) {
        // load A tile (128x16) transposed into As[k][m]
        #pragma unroll
        for (int i = 0; i < 2; i++) {
            int idx = tid + i * 256;         // 0..511
            int row = idx >> 2;              // 0..127
            int c4  = (idx & 3) << 2;        // 0,4,8,12
            float4 av = *(const float4*)(Aptr + (size_t)row * Kdim + k0 + c4);
            As[c4 + 0][row] = av.x;
            As[c4 + 1][row] = av.y;
            As[c4 + 2][row] = av.z;
            As[c4 + 3][row] = av.w;
        }
        // load B tile (16x128) direct
        #pragma unroll
        for (int i = 0; i < 2; i++) {
            int idx = tid + i * 256;         // 0..511
            int row = idx >> 5;              // 0..15
            int c4  = (idx & 31) << 2;       // 0..124
            *(float4*)&Bs[row][c4] =
                *(const float4*)(Bptr + (size_t)(k0 + row) * Ndim + c4);
        }
        __syncthreads();
        #pragma unroll
        for (int k = 0; k < GBK; k++) {
            float af[8], bf[8];
            *(float4*)&af[0] = *(const float4*)&As[k][ty * 8];
            *(float4*)&af[4] = *(const float4*)&As[k][ty * 8 + 4];
            *(float4*)&bf[0] = *(const float4*)&Bs[k][tx * 8];
            *(float4*)&bf[4] = *(const float4*)&Bs[k][tx * 8 + 4];
            #pragma unroll
            for (int i = 0; i < 8; i++)
                #pragma unroll
                for (int j = 0; j < 8; j++) acc[i][j] += af[i] * bf[j];
        }
        __syncthreads();
    }

    // epilogue
    int ocol = bx * GBN + tx * 8;
    float bia[8];
    #pragma unroll
    for (int j = 0; j < 8; j++) bia[j] = bias ? bias[ocol + j] : 0.f;
    #pragma unroll
    for (int i = 0; i < 8; i++) {
        int orow = by * GBM + ty * 8 + i;
        float* cp = C + (size_t)orow * Ndim + ocol;
        const float* ci = Cin + (size_t)orow * Ndim + ocol;
        float r[8];
        #pragma unroll
        for (int j = 0; j < 8; j++) {
            float x = acc[i][j] + bia[j];
            if (flags & 1) x += ci[j];
            if (flags & 2) x = fmaxf(x, 0.f);
            r[j] = x;
        }
        *(float4*)&cp[0] = *(float4*)&r[0];
        *(float4*)&cp[4] = *(float4*)&r[4];
    }
}

// ---------------- driver ----------------
extern "C" void kernel_launch(void* const* d_in, const int* in_sizes, int n_in,
                              void* d_out, int out_size) {
    const int*   input_x = (const int*)  d_in[0];
    const float* emb     = (const float*)d_in[1];
    const float* theta   = (const float*)d_in[2];
    const float* Wx      = (const float*)d_in[3];
    const float* bx_     = (const float*)d_in[4];
    const float* Wv      = (const float*)d_in[5];
    const float* bv      = (const float*)d_in[6];
    const float* Wh      = (const float*)d_in[7];
    const float* bh      = (const float*)d_in[8];
    const float* ln_g    = (const float*)d_in[9];
    const float* ln_b    = (const float*)d_in[10];
    const float* lnf_g   = (const float*)d_in[11];
    const float* lnf_b   = (const float*)d_in[12];
    const float* Wo1     = (const float*)d_in[13];
    const float* bo1     = (const float*)d_in[14];
    const float* Wo2     = (const float*)d_in[15];
    const float* bo2     = (const float*)d_in[16];

    float *a, *xn, *u, *v;
    cudaGetSymbolAddress((void**)&a,  g_a);
    cudaGetSymbolAddress((void**)&xn, g_xn);
    cudaGetSymbolAddress((void**)&u,  g_u);
    cudaGetSymbolAddress((void**)&v,  g_v);

    dim3 gemm_grid_DD(Dd / GBN, ROWS / GBM);   // (8, 256)
    dim3 gemm_grid_DV(Vv / GBN, ROWS / GBM);   // (1, 256)

    // embedding
    embed_kernel<<<ROWS, 256>>>(input_x, emb, a);

    for (int l = 0; l < Ll; l++) {
        const float* th  = theta + (size_t)l * NB;
        const float* wx  = Wx + (size_t)l * Dd * Dd;
        const float* wv  = Wv + (size_t)l * Dd * Dd;
        const float* wh  = Wh + (size_t)l * Dd * Dd;
        // layernorm
        ln_kernel<<<ROWS, 256>>>(a, ln_g + (size_t)l * Dd, ln_b + (size_t)l * Dd, xn);
        // u = xn @ Wx + bx ; v = xn @ Wv + bv
        gemm_kernel<<<gemm_grid_DD, 256>>>(xn, wx, bx_ + (size_t)l * Dd, nullptr, u,
                                           ROWS, Dd, Dd, 0);
        gemm_kernel<<<gemm_grid_DD, 256>>>(xn, wv, bv + (size_t)l * Dd, nullptr, v,
                                           ROWS, Dd, Dd, 0);
        // scan + gate (in place into u)
        scan_kernel<<<(Bb * NB) / 256, 256>>>(u, v, th);
        // a = (h*v) @ Wh + bh (+ a residual, except last layer)
        int flags = (l < Ll - 1) ? 1 : 0;
        gemm_kernel<<<gemm_grid_DD, 256>>>(u, wh, bh + (size_t)l * Dd, a, a,
                                           ROWS, Dd, Dd, flags);
    }

    // final layernorm
    ln_kernel<<<ROWS, 256>>>(a, lnf_g, lnf_b, xn);
    // t1 = relu(xn @ Wo1 + bo1)   (into u)
    gemm_kernel<<<gemm_grid_DD, 256>>>(xn, Wo1, bo1, nullptr, u,
                                       ROWS, Dd, Dd, 2);
    // out = t1 @ Wo2 + bo2
    gemm_kernel<<<gemm_grid_DV, 256>>>(u, Wo2, bo2, nullptr, (float*)d_out,
                                       ROWS, Vv, Dd, 0);
}

// round 3
// speedup vs baseline: 1.8636x; 1.8636x over previous
#include <cuda_runtime.h>
#include <cuda_bf16.h>
#include <cstdint>

// Problem constants
#define Bb 16
#define Ss 2048
#define Dd 1024
#define Vv 128          // vocab
#define Ll 4
#define NB (Dd/2)       // rotation blocks = 512
#define ROWS (Bb*Ss)    // 32768
#define DD2 (Dd*Dd)     // 1048576

// ---------------- scratch (device globals; no allocation allowed) ----------
__device__ float g_a [ROWS*Dd];            // residual stream (fp32)
__device__ float g_u [ROWS*Dd];            // x@Wx (fp32, scan input)
__device__ float g_v [ROWS*Dd];            // x@Wv (fp32, scan input)
__device__ __nv_bfloat16 g_xh[ROWS*Dd];    // LN output hi
__device__ __nv_bfloat16 g_xl[ROWS*Dd];    // LN output lo
__device__ __nv_bfloat16 g_gh[ROWS*Dd];    // gate / relu-out hi
__device__ __nv_bfloat16 g_gl[ROWS*Dd];    // gate / relu-out lo
// transposed+split weights: slots 0..11 = Wx0-3,Wv0-3,Wh0-3 ; 12 = Wo1 ; 13 = Wo2
__device__ __nv_bfloat16 g_wth[13*DD2 + Vv*Dd];
__device__ __nv_bfloat16 g_wtl[13*DD2 + Vv*Dd];

__device__ __forceinline__ void split_bf16(float x, __nv_bfloat16& h, __nv_bfloat16& l) {
    h = __float2bfloat16(x);
    l = __float2bfloat16(x - __bfloat162float(h));
}

// ---------------- embedding gather ----------------
__global__ __launch_bounds__(256) void embed_kernel(const int* __restrict__ idx,
                                                    const float* __restrict__ emb,
                                                    float* __restrict__ a) {
    int i = blockIdx.x * 256 + threadIdx.x;
    int row = i >> 8;                               // D/4 = 256
    int col = i & 255;
    int tok = idx[row];
    ((float4*)a)[i] = ((const float4*)emb)[tok * 256 + col];
}

// ---------------- weight transpose + split: W[K][N] -> Wt_hi/lo[N][K] ------
__global__ __launch_bounds__(256) void tsplit_kernel(const float* __restrict__ W,
                                                     int Kdim, int Ndim,
                                                     __nv_bfloat16* __restrict__ th,
                                                     __nv_bfloat16* __restrict__ tl) {
    __shared__ float tile[32][33];
    int n0 = blockIdx.x * 32, k0 = blockIdx.y * 32;
    int tx = threadIdx.x & 31, ty = threadIdx.x >> 5;   // ty 0..7
    #pragma unroll
    for (int i = 0; i < 4; i++)
        tile[ty + i * 8][tx] = W[(size_t)(k0 + ty + i * 8) * Ndim + n0 + tx];
    __syncthreads();
    #pragma unroll
    for (int i = 0; i < 4; i++) {
        float x = tile[tx][ty + i * 8];
        __nv_bfloat16 h, l;
        split_bf16(x, h, l);
        size_t o = (size_t)(n0 + ty + i * 8) * Kdim + k0 + tx;
        th[o] = h;
        tl[o] = l;
    }
}

// ---------------- layernorm -> split bf16 ----------------
__global__ __launch_bounds__(256) void ln_kernel(const float* __restrict__ x,
                                                 const float* __restrict__ gamma,
                                                 const float* __restrict__ beta,
                                                 __nv_bfloat16* __restrict__ yh,
                                                 __nv_bfloat16* __restrict__ yl) {
    __shared__ float red_s[8];
    __shared__ float red_q[8];
    int row = blockIdx.x;
    int t = threadIdx.x;
    float4 v = ((const float4*)(x + (size_t)row * Dd))[t];
    float s  = v.x + v.y + v.z + v.w;
    float ss = v.x*v.x + v.y*v.y + v.z*v.z + v.w*v.w;
    #pragma unroll
    for (int o = 16; o > 0; o >>= 1) {
        s  += __shfl_xor_sync(0xffffffff, s,  o);
        ss += __shfl_xor_sync(0xffffffff, ss, o);
    }
    if ((t & 31) == 0) { red_s[t >> 5] = s; red_q[t >> 5] = ss; }
    __syncthreads();
    if (t < 8) { s = red_s[t]; ss = red_q[t]; }
    if (t < 32) {
        #pragma unroll
        for (int o = 4; o > 0; o >>= 1) {
            s  += __shfl_xor_sync(0xffffffff, s,  o);
            ss += __shfl_xor_sync(0xffffffff, ss, o);
        }
        if (t == 0) { red_s[0] = s; red_q[0] = ss; }
    }
    __syncthreads();
    float mu  = red_s[0] * (1.0f / Dd);
    float var = red_q[0] * (1.0f / Dd) - mu * mu;
    float inv = rsqrtf(var + 1e-5f);
    float4 g4 = ((const float4*)gamma)[t];
    float4 b4 = ((const float4*)beta)[t];
    float o0 = (v.x - mu) * inv * g4.x + b4.x;
    float o1 = (v.y - mu) * inv * g4.y + b4.y;
    float o2 = (v.z - mu) * inv * g4.z + b4.z;
    float o3 = (v.w - mu) * inv * g4.w + b4.w;
    __nv_bfloat16 h0,h1,h2,h3,l0,l1,l2,l3;
    split_bf16(o0,h0,l0); split_bf16(o1,h1,l1);
    split_bf16(o2,h2,l2); split_bf16(o3,h3,l3);
    __nv_bfloat162* ph = (__nv_bfloat162*)(yh + (size_t)row * Dd);
    __nv_bfloat162* pl = (__nv_bfloat162*)(yl + (size_t)row * Dd);
    __nv_bfloat162 a2, b2;
    a2.x = h0; a2.y = h1; b2.x = h2; b2.y = h3;
    ph[t*2] = a2; ph[t*2+1] = b2;
    a2.x = l0; a2.y = l1; b2.x = l2; b2.y = l3;
    pl[t*2] = a2; pl[t*2+1] = b2;
}

// ---------------- linear-RNN scan; writes gate split bf16 ----------------
__global__ __launch_bounds__(256) void scan_kernel(const float* __restrict__ u,
                                                   const float* __restrict__ v,
                                                   const float* __restrict__ theta,
                                                   __nv_bfloat16* __restrict__ gh,
                                                   __nv_bfloat16* __restrict__ gl) {
    int tid = blockIdx.x * 256 + threadIdx.x;   // 0 .. B*NB-1
    int b   = tid / NB;
    int blk = tid % NB;
    float th = theta[blk];
    float c = cosf(th), sn = sinf(th);
    float hx = 0.f, hy = 0.f;
    size_t base = (size_t)b * Ss * (Dd / 2) + blk;   // float2 / bf162 units
    const float2*   up  = (const float2*)u + base;
    const float2*   vp  = (const float2*)v + base;
    __nv_bfloat162* ghp = (__nv_bfloat162*)gh + base;
    __nv_bfloat162* glp = (__nv_bfloat162*)gl + base;
    for (int s0 = 0; s0 < Ss; s0 += 8) {
        float2 ub[8], vb[8];
        #pragma unroll
        for (int j = 0; j < 8; j++) {
            ub[j] = up[(size_t)(s0 + j) * (Dd / 2)];
            vb[j] = vp[(size_t)(s0 + j) * (Dd / 2)];
        }
        #pragma unroll
        for (int j = 0; j < 8; j++) {
            float nx = c * hx - sn * hy + ub[j].x;
            float ny = sn * hx + c  * hy + ub[j].y;
            hx = nx; hy = ny;
            float gx = hx * vb[j].x;
            float gy = hy * vb[j].y;
            __nv_bfloat16 hgx, hgy, lgx, lgy;
            split_bf16(gx, hgx, lgx);
            split_bf16(gy, hgy, lgy);
            __nv_bfloat162 hh, ll;
            hh.x = hgx; hh.y = hgy;
            ll.x = lgx; ll.y = lgy;
            ghp[(size_t)(s0 + j) * (Dd / 2)] = hh;
            glp[(size_t)(s0 + j) * (Dd / 2)] = ll;
        }
    }
}

// ---------------- bf16x3 split GEMM ----------------
// C = A @ B^T-stored + bias, where A hi/lo [M][K], B hi/lo [N][K] (pre-transposed)
// flags: 1 = add Cin ; 2 = relu ; 4 = write split bf16 to (Chi,Clo) instead of C
#define SROW 24   // halves per smem row (16 data + 8 pad -> 48B, 16B-aligned, conflict-free)

__device__ __forceinline__ void cp_async16(void* smem, const void* gmem) {
    uint32_t s = (uint32_t)__cvta_generic_to_shared(smem);
    asm volatile("cp.async.cg.shared.global [%0], [%1], 16;\n" :: "r"(s), "l"(gmem));
}

#define MMA_BF16(ac, a, b) \
    asm volatile("mma.sync.aligned.m16n8k16.row.col.f32.bf16.bf16.f32 " \
                 "{%0,%1,%2,%3},{%4,%5,%6,%7},{%8,%9},{%0,%1,%2,%3};\n" \
                 : "+f"(ac[0]), "+f"(ac[1]), "+f"(ac[2]), "+f"(ac[3]) \
                 : "r"(a[0]), "r"(a[1]), "r"(a[2]), "r"(a[3]), "r"(b[0]), "r"(b[1]))

__global__ __launch_bounds__(256) void gemm_bf16x3_kernel(
        const __nv_bfloat16* __restrict__ Ah, const __nv_bfloat16* __restrict__ Al,
        const __nv_bfloat16* __restrict__ Bh, const __nv_bfloat16* __restrict__ Bl,
        const float* __restrict__ bias, const float* __restrict__ Cin,
        float* __restrict__ C,
        __nv_bfloat16* __restrict__ Chi, __nv_bfloat16* __restrict__ Clo,
        int Ndim, int Kdim, int flags) {
    __shared__ __align__(16) __nv_bfloat16 sAh[2][128 * SROW];
    __shared__ __align__(16) __nv_bfloat16 sAl[2][128 * SROW];
    __shared__ __align__(16) __nv_bfloat16 sBh[2][128 * SROW];
    __shared__ __align__(16) __nv_bfloat16 sBl[2][128 * SROW];

    int bx = blockIdx.x;            // N tile
    int by = blockIdx.y;            // M tile
    int tid = threadIdx.x;
    int warp = tid >> 5;
    int lane = tid & 31;
    int g = lane >> 2;              // 0..7
    int q = lane & 3;               // 0..3
    int warpM = (warp & 1) * 64;
    int warpN = (warp >> 1) * 32;

    float acc[4][4][4];
    #pragma unroll
    for (int i = 0; i < 4; i++)
        #pragma unroll
        for (int j = 0; j < 4; j++)
            #pragma unroll
            for (int r = 0; r < 4; r++) acc[i][j][r] = 0.f;

    const int NIT = Kdim / 16;
    int lm = tid >> 1;                 // 0..127 (tile row)
    int hsel = (tid & 1) * 8;          // 0 or 8 halves
    size_t arow = (size_t)(by * 128 + lm) * Kdim;
    size_t brow = (size_t)(bx * 128 + lm) * Kdim;
    uint32_t dsto = lm * SROW + hsel;

    auto load_stage = [&](int it, int st) {
        size_t ko = (size_t)it * 16 + hsel;
        cp_async16(&sAh[st][dsto], Ah + arow + ko);
        cp_async16(&sAl[st][dsto], Al + arow + ko);
        cp_async16(&sBh[st][dsto], Bh + brow + ko);
        cp_async16(&sBl[st][dsto], Bl + brow + ko);
        asm volatile("cp.async.commit_group;\n");
    };

    load_stage(0, 0);

    for (int it = 0; it < NIT; it++) {
        int st = it & 1;
        if (it + 1 < NIT) {
            load_stage(it + 1, (it + 1) & 1);
            asm volatile("cp.async.wait_group 1;\n");
        } else {
            asm volatile("cp.async.wait_group 0;\n");
        }
        __syncthreads();

        const uint32_t* pAh = (const uint32_t*)&sAh[st][0];
        const uint32_t* pAl = (const uint32_t*)&sAl[st][0];
        const uint32_t* pBh = (const uint32_t*)&sBh[st][0];
        const uint32_t* pBl = (const uint32_t*)&sBl[st][0];

        uint32_t af[4][4], bfh[4][2];
        #pragma unroll
        for (int i = 0; i < 4; i++) {
            int m0 = warpM + i * 16 + g;
            af[i][0] = pAh[(m0    ) * 12 + q];
            af[i][1] = pAh[(m0 + 8) * 12 + q];
            af[i][2] = pAh[(m0    ) * 12 + q + 4];
            af[i][3] = pAh[(m0 + 8) * 12 + q + 4];
        }
        #pragma unroll
        for (int j = 0; j < 4; j++) {
            int n0 = warpN + j * 8 + g;
            bfh[j][0] = pBh[n0 * 12 + q];
            bfh[j][1] = pBh[n0 * 12 + q + 4];
        }
        // pass 1: hi * hi
        #pragma unroll
        for (int i = 0; i < 4; i++)
            #pragma unroll
            for (int j = 0; j < 4; j++) MMA_BF16(acc[i][j], af[i], bfh[j]);
        // pass 2: hi * lo
        {
            uint32_t bfl[4][2];
            #pragma unroll
            for (int j = 0; j < 4; j++) {
                int n0 = warpN + j * 8 + g;
                bfl[j][0] = pBl[n0 * 12 + q];
                bfl[j][1] = pBl[n0 * 12 + q + 4];
            }
            #pragma unroll
            for (int i = 0; i < 4; i++)
                #pragma unroll
                for (int j = 0; j < 4; j++) MMA_BF16(acc[i][j], af[i], bfl[j]);
        }
        // pass 3: lo * hi  (reuse af registers)
        #pragma unroll
        for (int i = 0; i < 4; i++) {
            int m0 = warpM + i * 16 + g;
            af[i][0] = pAl[(m0    ) * 12 + q];
            af[i][1] = pAl[(m0 + 8) * 12 + q];
            af[i][2] = pAl[(m0    ) * 12 + q + 4];
            af[i][3] = pAl[(m0 + 8) * 12 + q + 4];
        }
        #pragma unroll
        for (int i = 0; i < 4; i++)
            #pragma unroll
            for (int j = 0; j < 4; j++) MMA_BF16(acc[i][j], af[i], bfh[j]);

        __syncthreads();
    }

    // epilogue
    #pragma unroll
    for (int i = 0; i < 4; i++) {
        int r0 = by * 128 + warpM + i * 16 + g;
        int r1 = r0 + 8;
        #pragma unroll
        for (int j = 0; j < 4; j++) {
            int cc = bx * 128 + warpN + j * 8 + (q << 1);
            float b0 = bias ? bias[cc]     : 0.f;
            float b1 = bias ? bias[cc + 1] : 0.f;
            float x0 = acc[i][j][0] + b0;
            float x1 = acc[i][j][1] + b1;
            float x2 = acc[i][j][2] + b0;
            float x3 = acc[i][j][3] + b1;
            if (flags & 1) {
                const float2 ci0 = *(const float2*)(Cin + (size_t)r0 * Ndim + cc);
                const float2 ci1 = *(const float2*)(Cin + (size_t)r1 * Ndim + cc);
                x0 += ci0.x; x1 += ci0.y; x2 += ci1.x; x3 += ci1.y;
            }
            if (flags & 2) {
                x0 = fmaxf(x0, 0.f); x1 = fmaxf(x1, 0.f);
                x2 = fmaxf(x2, 0.f); x3 = fmaxf(x3, 0.f);
            }
            if (flags & 4) {
                __nv_bfloat16 h0,h1,h2,h3,l0,l1,l2,l3;
                split_bf16(x0,h0,l0); split_bf16(x1,h1,l1);
                split_bf16(x2,h2,l2); split_bf16(x3,h3,l3);
                __nv_bfloat162 t2;
                t2.x = h0; t2.y = h1;
                *(__nv_bfloat162*)(Chi + (size_t)r0 * Ndim + cc) = t2;
                t2.x = h2; t2.y = h3;
                *(__nv_bfloat162*)(Chi + (size_t)r1 * Ndim + cc) = t2;
                t2.x = l0; t2.y = l1;
                *(__nv_bfloat162*)(Clo + (size_t)r0 * Ndim + cc) = t2;
                t2.x = l2; t2.y = l3;
                *(__nv_bfloat162*)(Clo + (size_t)r1 * Ndim + cc) = t2;
            } else {
                *(float2*)(C + (size_t)r0 * Ndim + cc) = make_float2(x0, x1);
                *(float2*)(C + (size_t)r1 * Ndim + cc) = make_float2(x2, x3);
            }
        }
    }
}

// ---------------- driver ----------------
extern "C" void kernel_launch(void* const* d_in, const int* in_sizes, int n_in,
                              void* d_out, int out_size) {
    const int*   input_x = (const int*)  d_in[0];
    const float* emb     = (const float*)d_in[1];
    const float* theta   = (const float*)d_in[2];
    const float* Wx      = (const float*)d_in[3];
    const float* bx_     = (const float*)d_in[4];
    const float* Wv      = (const float*)d_in[5];
    const float* bv      = (const float*)d_in[6];
    const float* Wh      = (const float*)d_in[7];
    const float* bh      = (const float*)d_in[8];
    const float* ln_g    = (const float*)d_in[9];
    const float* ln_b    = (const float*)d_in[10];
    const float* lnf_g   = (const float*)d_in[11];
    const float* lnf_b   = (const float*)d_in[12];
    const float* Wo1     = (const float*)d_in[13];
    const float* bo1     = (const float*)d_in[14];
    const float* Wo2     = (const float*)d_in[15];
    const float* bo2     = (const float*)d_in[16];

    float *a, *u, *v;
    __nv_bfloat16 *xh, *xl, *gh, *gl, *wth, *wtl;
    cudaGetSymbolAddress((void**)&a,  g_a);
    cudaGetSymbolAddress((void**)&u,  g_u);
    cudaGetSymbolAddress((void**)&v,  g_v);
    cudaGetSymbolAddress((void**)&xh, g_xh);
    cudaGetSymbolAddress((void**)&xl, g_xl);
    cudaGetSymbolAddress((void**)&gh, g_gh);
    cudaGetSymbolAddress((void**)&gl, g_gl);
    cudaGetSymbolAddress((void**)&wth, g_wth);
    cudaGetSymbolAddress((void**)&wtl, g_wtl);

    dim3 tg(Dd / 32, Dd / 32);
    // weight transpose+split: slots 0..11 layer weights, 12 = Wo1, 13 = Wo2
    for (int l = 0; l < Ll; l++) {
        tsplit_kernel<<<tg, 256>>>(Wx + (size_t)l * DD2, Dd, Dd,
                                   wth + (size_t)(0 + l) * DD2, wtl + (size_t)(0 + l) * DD2);
        tsplit_kernel<<<tg, 256>>>(Wv + (size_t)l * DD2, Dd, Dd,
                                   wth + (size_t)(4 + l) * DD2, wtl + (size_t)(4 + l) * DD2);
        tsplit_kernel<<<tg, 256>>>(Wh + (size_t)l * DD2, Dd, Dd,
                                   wth + (size_t)(8 + l) * DD2, wtl + (size_t)(8 + l) * DD2);
    }
    tsplit_kernel<<<tg, 256>>>(Wo1, Dd, Dd, wth + (size_t)12 * DD2, wtl + (size_t)12 * DD2);
    dim3 tg2(Vv / 32, Dd / 32);
    tsplit_kernel<<<tg2, 256>>>(Wo2, Dd, Vv, wth + (size_t)13 * DD2, wtl + (size_t)13 * DD2);

    embed_kernel<<<ROWS, 256>>>(input_x, emb, a);

    dim3 grid_DD(Dd / 128, ROWS / 128);   // (8, 256)
    dim3 grid_DV(Vv / 128, ROWS / 128);   // (1, 256)

    for (int l = 0; l < Ll; l++) {
        const __nv_bfloat16* wxh = wth + (size_t)(0 + l) * DD2;
        const __nv_bfloat16* wxl = wtl + (size_t)(0 + l) * DD2;
        const __nv_bfloat16* wvh = wth + (size_t)(4 + l) * DD2;
        const __nv_bfloat16* wvl = wtl + (size_t)(4 + l) * DD2;
        const __nv_bfloat16* whh = wth + (size_t)(8 + l) * DD2;
        const __nv_bfloat16* whl = wtl + (size_t)(8 + l) * DD2;

        ln_kernel<<<ROWS, 256>>>(a, ln_g + (size_t)l * Dd, ln_b + (size_t)l * Dd, xh, xl);
        gemm_bf16x3_kernel<<<grid_DD, 256>>>(xh, xl, wxh, wxl,
                                             bx_ + (size_t)l * Dd, nullptr,
                                             u, nullptr, nullptr, Dd, Dd, 0);
        gemm_bf16x3_kernel<<<grid_DD, 256>>>(xh, xl, wvh, wvl,
                                             bv + (size_t)l * Dd, nullptr,
                                             v, nullptr, nullptr, Dd, Dd, 0);
        scan_kernel<<<(Bb * NB) / 256, 256>>>(u, v, theta + (size_t)l * NB, gh, gl);
        int flags = (l < Ll - 1) ? 1 : 0;
        gemm_bf16x3_kernel<<<grid_DD, 256>>>(gh, gl, whh, whl,
                                             bh + (size_t)l * Dd, a,
                                             a, nullptr, nullptr, Dd, Dd, flags);
    }

    ln_kernel<<<ROWS, 256>>>(a, lnf_g, lnf_b, xh, xl);
    // relu(xn @ Wo1 + bo1) -> split into gh/gl
    gemm_bf16x3_kernel<<<grid_DD, 256>>>(xh, xl, wth + (size_t)12 * DD2, wtl + (size_t)12 * DD2,
                                         bo1, nullptr,
                                         nullptr, gh, gl, Dd, Dd, 2 | 4);
    // out = gate @ Wo2 + bo2
    gemm_bf16x3_kernel<<<grid_DV, 256>>>(gh, gl, wth + (size_t)13 * DD2, wtl + (size_t)13 * DD2,
                                         bo2, nullptr,
                                         (float*)d_out, nullptr, nullptr, Vv, Dd, 0);
}

// round 6
// speedup vs baseline: 2.0081x; 1.0775x over previous
#include <cuda_runtime.h>
#include <cuda_bf16.h>
#include <cstdint>

// Problem constants
#define Bb 16
#define Ss 2048
#define Dd 1024
#define Vv 128          // vocab
#define Ll 4
#define NB (Dd/2)       // rotation blocks = 512
#define ROWS (Bb*Ss)    // 32768
#define DD2 (Dd*Dd)     // 1048576

// ---------------- scratch (device globals; no allocation allowed) ----------
__device__ float g_a [ROWS*Dd];            // residual stream (fp32)
__device__ float g_u [ROWS*Dd];            // x@Wx (fp32, scan input)
__device__ float g_v [ROWS*Dd];            // x@Wv (fp32, scan input)
__device__ __nv_bfloat16 g_xh[ROWS*Dd];    // LN output hi
__device__ __nv_bfloat16 g_xl[ROWS*Dd];    // LN output lo
__device__ __nv_bfloat16 g_gh[ROWS*Dd];    // gate / relu-out hi
__device__ __nv_bfloat16 g_gl[ROWS*Dd];    // gate / relu-out lo
// transposed+split weights: slots 0..3 Wx, 4..7 Wv, 8..11 Wh, 12 Wo1, 13 Wo2
__device__ __nv_bfloat16 g_wth[13*DD2 + Vv*Dd];
__device__ __nv_bfloat16 g_wtl[13*DD2 + Vv*Dd];

__device__ __forceinline__ void split_bf16(float x, __nv_bfloat16& h, __nv_bfloat16& l) {
    h = __float2bfloat16(x);
    l = __float2bfloat16(x - __bfloat162float(h));
}

// ---------------- embedding gather ----------------
__global__ __launch_bounds__(256) void embed_kernel(const int* __restrict__ idx,
                                                    const float* __restrict__ emb,
                                                    float* __restrict__ a) {
    int i = blockIdx.x * 256 + threadIdx.x;
    int row = i >> 8;
    int col = i & 255;
    int tok = idx[row];
    ((float4*)a)[i] = ((const float4*)emb)[tok * 256 + col];
}

// ---------------- batched weight transpose + split ----------------
// Transposes W[K][N] -> Wt hi/lo [N][K] for a range of weight slots.
__global__ __launch_bounds__(256) void tsplit_all_kernel(
        const float* __restrict__ Wx, const float* __restrict__ Wv,
        const float* __restrict__ Wh, const float* __restrict__ Wo1,
        const float* __restrict__ Wo2,
        __nv_bfloat16* __restrict__ wth, __nv_bfloat16* __restrict__ wtl,
        int slot0) {
    __shared__ float tile[32][33];
    int slot = slot0 + blockIdx.z;
    const float* W;
    int Ndim = Dd;
    if (slot < 4)       W = Wx + (size_t)slot * DD2;
    else if (slot < 8)  W = Wv + (size_t)(slot - 4) * DD2;
    else if (slot < 12) W = Wh + (size_t)(slot - 8) * DD2;
    else if (slot == 12) W = Wo1;
    else { W = Wo2; Ndim = Vv; }
    __nv_bfloat16* th = wth + (size_t)slot * DD2;
    __nv_bfloat16* tl = wtl + (size_t)slot * DD2;

    int n0 = blockIdx.x * 32, k0 = blockIdx.y * 32;
    if (n0 >= Ndim) return;
    int tx = threadIdx.x & 31, ty = threadIdx.x >> 5;
    #pragma unroll
    for (int i = 0; i < 4; i++)
        tile[ty + i * 8][tx] = W[(size_t)(k0 + ty + i * 8) * Ndim + n0 + tx];
    __syncthreads();
    #pragma unroll
    for (int i = 0; i < 4; i++) {
        float x = tile[tx][ty + i * 8];
        __nv_bfloat16 h, l;
        split_bf16(x, h, l);
        size_t o = (size_t)(n0 + ty + i * 8) * Dd + k0 + tx;
        th[o] = h;
        tl[o] = l;
    }
}

// ---------------- layernorm -> split bf16 ----------------
__global__ __launch_bounds__(256) void ln_kernel(const float* __restrict__ x,
                                                 const float* __restrict__ gamma,
                                                 const float* __restrict__ beta,
                                                 __nv_bfloat16* __restrict__ yh,
                                                 __nv_bfloat16* __restrict__ yl) {
    __shared__ float red_s[8];
    __shared__ float red_q[8];
    int row = blockIdx.x;
    int t = threadIdx.x;
    float4 v = ((const float4*)(x + (size_t)row * Dd))[t];
    float s  = v.x + v.y + v.z + v.w;
    float ss = v.x*v.x + v.y*v.y + v.z*v.z + v.w*v.w;
    #pragma unroll
    for (int o = 16; o > 0; o >>= 1) {
        s  += __shfl_xor_sync(0xffffffff, s,  o);
        ss += __shfl_xor_sync(0xffffffff, ss, o);
    }
    if ((t & 31) == 0) { red_s[t >> 5] = s; red_q[t >> 5] = ss; }
    __syncthreads();
    if (t < 8) { s = red_s[t]; ss = red_q[t]; }
    if (t < 32) {
        #pragma unroll
        for (int o = 4; o > 0; o >>= 1) {
            s  += __shfl_xor_sync(0xffffffff, s,  o);
            ss += __shfl_xor_sync(0xffffffff, ss, o);
        }
        if (t == 0) { red_s[0] = s; red_q[0] = ss; }
    }
    __syncthreads();
    float mu  = red_s[0] * (1.0f / Dd);
    float var = red_q[0] * (1.0f / Dd) - mu * mu;
    float inv = rsqrtf(var + 1e-5f);
    float4 g4 = ((const float4*)gamma)[t];
    float4 b4 = ((const float4*)beta)[t];
    float o0 = (v.x - mu) * inv * g4.x + b4.x;
    float o1 = (v.y - mu) * inv * g4.y + b4.y;
    float o2 = (v.z - mu) * inv * g4.z + b4.z;
    float o3 = (v.w - mu) * inv * g4.w + b4.w;
    __nv_bfloat16 h0,h1,h2,h3,l0,l1,l2,l3;
    split_bf16(o0,h0,l0); split_bf16(o1,h1,l1);
    split_bf16(o2,h2,l2); split_bf16(o3,h3,l3);
    __nv_bfloat162* ph = (__nv_bfloat162*)(yh + (size_t)row * Dd);
    __nv_bfloat162* pl = (__nv_bfloat162*)(yl + (size_t)row * Dd);
    __nv_bfloat162 a2, b2;
    a2.x = h0; a2.y = h1; b2.x = h2; b2.y = h3;
    ph[t*2] = a2; ph[t*2+1] = b2;
    a2.x = l0; a2.y = l1; b2.x = l2; b2.y = l3;
    pl[t*2] = a2; pl[t*2+1] = b2;
}

// ---------------- linear-RNN scan; writes gate split bf16 ----------------
__global__ __launch_bounds__(256) void scan_kernel(const float* __restrict__ u,
                                                   const float* __restrict__ v,
                                                   const float* __restrict__ theta,
                                                   __nv_bfloat16* __restrict__ gh,
                                                   __nv_bfloat16* __restrict__ gl) {
    int tid = blockIdx.x * 256 + threadIdx.x;
    int b   = tid / NB;
    int blk = tid % NB;
    float th = theta[blk];
    float c = cosf(th), sn = sinf(th);
    float hx = 0.f, hy = 0.f;
    size_t base = (size_t)b * Ss * (Dd / 2) + blk;
    const float2*   up  = (const float2*)u + base;
    const float2*   vp  = (const float2*)v + base;
    __nv_bfloat162* ghp = (__nv_bfloat162*)gh + base;
    __nv_bfloat162* glp = (__nv_bfloat162*)gl + base;
    for (int s0 = 0; s0 < Ss; s0 += 8) {
        float2 ub[8], vb[8];
        #pragma unroll
        for (int j = 0; j < 8; j++) {
            ub[j] = up[(size_t)(s0 + j) * (Dd / 2)];
            vb[j] = vp[(size_t)(s0 + j) * (Dd / 2)];
        }
        #pragma unroll
        for (int j = 0; j < 8; j++) {
            float nx = c * hx - sn * hy + ub[j].x;
            float ny = sn * hx + c  * hy + ub[j].y;
            hx = nx; hy = ny;
            float gx = hx * vb[j].x;
            float gy = hy * vb[j].y;
            __nv_bfloat16 hgx, hgy, lgx, lgy;
            split_bf16(gx, hgx, lgx);
            split_bf16(gy, hgy, lgy);
            __nv_bfloat162 hh, ll;
            hh.x = hgx; hh.y = hgy;
            ll.x = lgx; ll.y = lgy;
            ghp[(size_t)(s0 + j) * (Dd / 2)] = hh;
            glp[(size_t)(s0 + j) * (Dd / 2)] = ll;
        }
    }
}

// ---------------- bf16x3 split GEMM (mma.sync + ldmatrix, 3-stage) --------
// C = A @ Bw^T + bias, A hi/lo [M][K], Bw hi/lo [N][K] (pre-transposed).
// CTA 128x128x16, 8 warps (2Mx4N), warp 64x32.
// Smem rows: 16 halves data + 8 pad = 48B stride (conflict-free LDS/LDSM).
#define SROWB 48                       // bytes per smem row
#define A_T   (128 * SROWB)            // 6144 B per operand region
#define STAGE (4 * A_T)                // Ah,Al,Bh,Bl = 24576 B
#define NSTG  3

__device__ __forceinline__ void cp_async16(uint32_t smem, const void* gmem) {
    asm volatile("cp.async.cg.shared.global [%0], [%1], 16;\n" :: "r"(smem), "l"(gmem));
}
__device__ __forceinline__ uint32_t smem_u32(const void* p) {
    uint32_t a;
    asm("{ .reg .u64 t; cvta.to.shared.u64 t, %1; cvt.u32.u64 %0, t; }"
        : "=r"(a) : "l"(p));
    return a;
}
#define LDSM4(r, addr) \
    asm volatile("ldmatrix.sync.aligned.m8n8.x4.shared.b16 {%0,%1,%2,%3}, [%4];" \
                 : "=r"((r)[0]), "=r"((r)[1]), "=r"((r)[2]), "=r"((r)[3]) \
                 : "r"(addr))
#define MMA_BF16(ac, a, b0, b1) \
    asm volatile("mma.sync.aligned.m16n8k16.row.col.f32.bf16.bf16.f32 " \
                 "{%0,%1,%2,%3},{%4,%5,%6,%7},{%8,%9},{%0,%1,%2,%3};\n" \
                 : "+f"((ac)[0]), "+f"((ac)[1]), "+f"((ac)[2]), "+f"((ac)[3]) \
                 : "r"((a)[0]), "r"((a)[1]), "r"((a)[2]), "r"((a)[3]), \
                   "r"(b0), "r"(b1))

__global__ __launch_bounds__(256, 2) void gemm_bf16x3_kernel(
        const __nv_bfloat16* __restrict__ Ah, const __nv_bfloat16* __restrict__ Al,
        const __nv_bfloat16* __restrict__ Bh, const __nv_bfloat16* __restrict__ Bl,
        const float* __restrict__ bias, const float* __restrict__ Cin,
        float* __restrict__ C,
        __nv_bfloat16* __restrict__ Chi, __nv_bfloat16* __restrict__ Clo,
        int Ndim, int Kdim, int flags) {
    extern __shared__ __align__(16) char smem[];
    const uint32_t sb = smem_u32(smem);

    int bx = blockIdx.x;            // N tile
    int by = blockIdx.y;            // M tile
    int tid = threadIdx.x;
    int warp = tid >> 5;
    int lane = tid & 31;
    int g = lane >> 2;              // 0..7
    int q = lane & 3;               // 0..3
    int warpM = (warp & 1) * 64;
    int warpN = (warp >> 1) * 32;

    // ldmatrix lane offsets (within an operand region, bytes)
    int r8  = lane & 7;
    int sub = lane >> 3;            // 0..3
    uint32_t aoff = (uint32_t)(((sub & 1) * 8 + r8) * SROWB + ((sub >> 1) * 8) * 2);
    uint32_t boff = (uint32_t)(((sub >> 1) * 8 + r8) * SROWB + ((sub & 1) * 8) * 2);

    float acc[4][4][4];
    #pragma unroll
    for (int i = 0; i < 4; i++)
        #pragma unroll
        for (int j = 0; j < 4; j++)
            #pragma unroll
            for (int r = 0; r < 4; r++) acc[i][j][r] = 0.f;

    const int NIT = Kdim / 16;
    int lm = tid >> 1;                 // 0..127 (tile row)
    int hsel = (tid & 1) * 8;          // 0 or 8 halves (16B chunk)
    size_t arow = (size_t)(by * 128 + lm) * Kdim;
    size_t brow = (size_t)(bx * 128 + lm) * Kdim;
    uint32_t dsto = (uint32_t)(lm * SROWB + hsel * 2);

    auto load_stage = [&](int it, int st) {
        uint32_t stg = sb + st * STAGE;
        size_t ko = (size_t)it * 16 + hsel;
        cp_async16(stg             + dsto, Ah + arow + ko);
        cp_async16(stg + A_T       + dsto, Al + arow + ko);
        cp_async16(stg + 2 * A_T   + dsto, Bh + brow + ko);
        cp_async16(stg + 3 * A_T   + dsto, Bl + brow + ko);
        asm volatile("cp.async.commit_group;\n");
    };

    load_stage(0, 0);
    load_stage(1, 1);

    for (int it = 0; it < NIT; it++) {
        int st = it % NSTG;
        if (it + 1 < NIT) {
            asm volatile("cp.async.wait_group 1;\n" ::: "memory");
        } else {
            asm volatile("cp.async.wait_group 0;\n" ::: "memory");
        }
        __syncthreads();

        uint32_t stg = sb + st * STAGE;
        uint32_t af[4][4], bfh[2][4], bfl[2][4];
        #pragma unroll
        for (int i = 0; i < 4; i++)
            LDSM4(af[i], stg + (uint32_t)((warpM + i * 16) * SROWB) + aoff);
        #pragma unroll
        for (int j2 = 0; j2 < 2; j2++)
            LDSM4(bfh[j2], stg + 2 * A_T + (uint32_t)((warpN + j2 * 16) * SROWB) + boff);
        #pragma unroll
        for (int j2 = 0; j2 < 2; j2++)
            LDSM4(bfl[j2], stg + 3 * A_T + (uint32_t)((warpN + j2 * 16) * SROWB) + boff);

        // pass 1: hi * hi
        #pragma unroll
        for (int i = 0; i < 4; i++)
            #pragma unroll
            for (int j = 0; j < 4; j++)
                MMA_BF16(acc[i][j], af[i], bfh[j >> 1][(j & 1) * 2], bfh[j >> 1][(j & 1) * 2 + 1]);
        // pass 2: hi * lo
        #pragma unroll
        for (int i = 0; i < 4; i++)
            #pragma unroll
            for (int j = 0; j < 4; j++)
                MMA_BF16(acc[i][j], af[i], bfl[j >> 1][(j & 1) * 2], bfl[j >> 1][(j & 1) * 2 + 1]);
        // pass 3: lo * hi (reload A from lo region, reuse af regs)
        #pragma unroll
        for (int i = 0; i < 4; i++)
            LDSM4(af[i], stg + A_T + (uint32_t)((warpM + i * 16) * SROWB) + aoff);
        #pragma unroll
        for (int i = 0; i < 4; i++)
            #pragma unroll
            for (int j = 0; j < 4; j++)
                MMA_BF16(acc[i][j], af[i], bfh[j >> 1][(j & 1) * 2], bfh[j >> 1][(j & 1) * 2 + 1]);

        __syncthreads();
        if (it + 2 < NIT) load_stage(it + 2, (it + 2) % NSTG);
    }

    // epilogue
    #pragma unroll
    for (int i = 0; i < 4; i++) {
        int r0 = by * 128 + warpM + i * 16 + g;
        int r1 = r0 + 8;
        #pragma unroll
        for (int j = 0; j < 4; j++) {
            int cc = bx * 128 + warpN + j * 8 + (q << 1);
            float b0 = bias ? bias[cc]     : 0.f;
            float b1 = bias ? bias[cc + 1] : 0.f;
            float x0 = acc[i][j][0] + b0;
            float x1 = acc[i][j][1] + b1;
            float x2 = acc[i][j][2] + b0;
            float x3 = acc[i][j][3] + b1;
            if (flags & 1) {
                const float2 ci0 = *(const float2*)(Cin + (size_t)r0 * Ndim + cc);
                const float2 ci1 = *(const float2*)(Cin + (size_t)r1 * Ndim + cc);
                x0 += ci0.x; x1 += ci0.y; x2 += ci1.x; x3 += ci1.y;
            }
            if (flags & 2) {
                x0 = fmaxf(x0, 0.f); x1 = fmaxf(x1, 0.f);
                x2 = fmaxf(x2, 0.f); x3 = fmaxf(x3, 0.f);
            }
            if (flags & 4) {
                __nv_bfloat16 h0,h1,h2,h3,l0,l1,l2,l3;
                split_bf16(x0,h0,l0); split_bf16(x1,h1,l1);
                split_bf16(x2,h2,l2); split_bf16(x3,h3,l3);
                __nv_bfloat162 t2;
                t2.x = h0; t2.y = h1;
                *(__nv_bfloat162*)(Chi + (size_t)r0 * Ndim + cc) = t2;
                t2.x = h2; t2.y = h3;
                *(__nv_bfloat162*)(Chi + (size_t)r1 * Ndim + cc) = t2;
                t2.x = l0; t2.y = l1;
                *(__nv_bfloat162*)(Clo + (size_t)r0 * Ndim + cc) = t2;
                t2.x = l2; t2.y = l3;
                *(__nv_bfloat162*)(Clo + (size_t)r1 * Ndim + cc) = t2;
            } else {
                *(float2*)(C + (size_t)r0 * Ndim + cc) = make_float2(x0, x1);
                *(float2*)(C + (size_t)r1 * Ndim + cc) = make_float2(x2, x3);
            }
        }
    }
}

// ---------------- driver ----------------
extern "C" void kernel_launch(void* const* d_in, const int* in_sizes, int n_in,
                              void* d_out, int out_size) {
    const int*   input_x = (const int*)  d_in[0];
    const float* emb     = (const float*)d_in[1];
    const float* theta   = (const float*)d_in[2];
    const float* Wx      = (const float*)d_in[3];
    const float* bx_     = (const float*)d_in[4];
    const float* Wv      = (const float*)d_in[5];
    const float* bv      = (const float*)d_in[6];
    const float* Wh      = (const float*)d_in[7];
    const float* bh      = (const float*)d_in[8];
    const float* ln_g    = (const float*)d_in[9];
    const float* ln_b    = (const float*)d_in[10];
    const float* lnf_g   = (const float*)d_in[11];
    const float* lnf_b   = (const float*)d_in[12];
    const float* Wo1     = (const float*)d_in[13];
    const float* bo1     = (const float*)d_in[14];
    const float* Wo2     = (const float*)d_in[15];
    const float* bo2     = (const float*)d_in[16];

    float *a, *u, *v;
    __nv_bfloat16 *xh, *xl, *gh, *gl, *wth, *wtl;
    cudaGetSymbolAddress((void**)&a,  g_a);
    cudaGetSymbolAddress((void**)&u,  g_u);
    cudaGetSymbolAddress((void**)&v,  g_v);
    cudaGetSymbolAddress((void**)&xh, g_xh);
    cudaGetSymbolAddress((void**)&xl, g_xl);
    cudaGetSymbolAddress((void**)&gh, g_gh);
    cudaGetSymbolAddress((void**)&gl, g_gl);
    cudaGetSymbolAddress((void**)&wth, g_wth);
    cudaGetSymbolAddress((void**)&wtl, g_wtl);

    const int GSMEM = NSTG * STAGE;   // 73728
    cudaFuncSetAttribute(gemm_bf16x3_kernel,
                         cudaFuncAttributeMaxDynamicSharedMemorySize, GSMEM);

    // weight prep: 2 launches (keeps first gemm at profiler capture index)
    tsplit_all_kernel<<<dim3(32, 32, 7), 256>>>(Wx, Wv, Wh, Wo1, Wo2, wth, wtl, 0);
    tsplit_all_kernel<<<dim3(32, 32, 7), 256>>>(Wx, Wv, Wh, Wo1, Wo2, wth, wtl, 7);

    embed_kernel<<<ROWS, 256>>>(input_x, emb, a);

    dim3 grid_DD(Dd / 128, ROWS / 128);   // (8, 256)
    dim3 grid_DV(Vv / 128, ROWS / 128);   // (1, 256)

    for (int l = 0; l < Ll; l++) {
        const __nv_bfloat16* wxh = wth + (size_t)(0 + l) * DD2;
        const __nv_bfloat16* wxl = wtl + (size_t)(0 + l) * DD2;
        const __nv_bfloat16* wvh = wth + (size_t)(4 + l) * DD2;
        const __nv_bfloat16* wvl = wtl + (size_t)(4 + l) * DD2;
        const __nv_bfloat16* whh = wth + (size_t)(8 + l) * DD2;
        const __nv_bfloat16* whl = wtl + (size_t)(8 + l) * DD2;

        ln_kernel<<<ROWS, 256>>>(a, ln_g + (size_t)l * Dd, ln_b + (size_t)l * Dd, xh, xl);
        gemm_bf16x3_kernel<<<grid_DD, 256, GSMEM>>>(xh, xl, wxh, wxl,
                bx_ + (size_t)l * Dd, nullptr, u, nullptr, nullptr, Dd, Dd, 0);
        gemm_bf16x3_kernel<<<grid_DD, 256, GSMEM>>>(xh, xl, wvh, wvl,
                bv + (size_t)l * Dd, nullptr, v, nullptr, nullptr, Dd, Dd, 0);
        scan_kernel<<<(Bb * NB) / 256, 256>>>(u, v, theta + (size_t)l * NB, gh, gl);
        int flags = (l < Ll - 1) ? 1 : 0;
        gemm_bf16x3_kernel<<<grid_DD, 256, GSMEM>>>(gh, gl, whh, whl,
                bh + (size_t)l * Dd, a, a, nullptr, nullptr, Dd, Dd, flags);
    }

    ln_kernel<<<ROWS, 256>>>(a, lnf_g, lnf_b, xh, xl);
    gemm_bf16x3_kernel<<<grid_DD, 256, GSMEM>>>(xh, xl,
            wth + (size_t)12 * DD2, wtl + (size_t)12 * DD2,
            bo1, nullptr, nullptr, gh, gl, Dd, Dd, 2 | 4);
    gemm_bf16x3_kernel<<<grid_DV, 256, GSMEM>>>(gh, gl,
            wth + (size_t)13 * DD2, wtl + (size_t)13 * DD2,
            bo2, nullptr, (float*)d_out, nullptr, nullptr, Vv, Dd, 0);
}

// round 7
// speedup vs baseline: 2.7629x; 1.3759x over previous
#include <cuda_runtime.h>
#include <cuda_bf16.h>
#include <cstdint>

// Problem constants
#define Bb 16
#define Ss 2048
#define Dd 1024
#define Vv 128          // vocab
#define Ll 4
#define NB (Dd/2)       // rotation blocks = 512
#define ROWS (Bb*Ss)    // 32768
#define DD2 (Dd*Dd)     // 1048576

// ---------------- scratch (device globals; no allocation allowed) ----------
__device__ float g_a [ROWS*Dd];     // residual stream
__device__ float g_u [ROWS*Dd];     // x@Wx
__device__ float g_v [ROWS*Dd];     // x@Wv
__device__ float g_w [ROWS*Dd];     // gate / relu out (fp32, pre-quant)
__device__ int8_t g_qa1[ROWS*Dd];   // activation digit 1
__device__ int8_t g_qa2[ROWS*Dd];   // activation digit 2
__device__ float  g_sa [ROWS];      // activation row scales
// transposed+quantized weights: slots 0..3 Wx, 4..7 Wv, 8..11 Wh, 12 Wo1, 13 Wo2
__device__ int8_t g_wq1[13*DD2 + Vv*Dd];
__device__ int8_t g_wq2[13*DD2 + Vv*Dd];
__device__ float  g_sw [14*Dd];     // weight row (=output col) scales

__device__ __forceinline__ int clampi(int x, int lo, int hi) {
    return x < lo ? lo : (x > hi ? hi : x);
}

// ---------------- embedding gather ----------------
__global__ __launch_bounds__(256) void embed_kernel(const int* __restrict__ idx,
                                                    const float* __restrict__ emb,
                                                    float* __restrict__ a) {
    int i = blockIdx.x * 256 + threadIdx.x;
    int row = i >> 8;
    int col = i & 255;
    int tok = idx[row];
    ((float4*)a)[i] = ((const float4*)emb)[tok * 256 + col];
}

// ---------------- weight transpose + 2-digit int8 quant ----------------
// W[K][N] (K=1024) -> per output-col n: q1,q2 [n][k], scale s[n].
// One block per (32-col chunk, slot). Two passes over gmem (max, then quant).
#define WQ_STRIDE 1040   // smem staging row stride (16B aligned, 4-way conflicts ok)
__global__ __launch_bounds__(256) void wquant_kernel(
        const float* __restrict__ Wx, const float* __restrict__ Wv,
        const float* __restrict__ Wh, const float* __restrict__ Wo1,
        const float* __restrict__ Wo2,
        int8_t* __restrict__ q1w, int8_t* __restrict__ q2w,
        float* __restrict__ sw, int slot0) {
    extern __shared__ char wsm[];
    char*  q1s  = wsm;                        // 32*1040
    char*  q2s  = wsm + 32 * WQ_STRIDE;       // 32*1040
    float* part = (float*)(wsm + 64 * WQ_STRIDE);   // 8*32
    float* cmax = part + 8 * 32;                    // 32

    int slot = slot0 + blockIdx.y;
    const float* W;
    int Ndim = Dd;
    if (slot < 4)        W = Wx + (size_t)slot * DD2;
    else if (slot < 8)   W = Wv + (size_t)(slot - 4) * DD2;
    else if (slot < 12)  W = Wh + (size_t)(slot - 8) * DD2;
    else if (slot == 12) W = Wo1;
    else { W = Wo2; Ndim = Vv; }

    int n0 = blockIdx.x * 32;
    if (n0 >= Ndim) return;
    int t = threadIdx.x;
    int tc = t & 31, tr = t >> 5;

    // pass 1: column max
    float m = 0.f;
    for (int k = tr; k < Dd; k += 8)
        m = fmaxf(m, fabsf(W[(size_t)k * Ndim + n0 + tc]));
    part[tr * 32 + tc] = m;
    __syncthreads();
    if (t < 32) {
        float mm = part[t];
        #pragma unroll
        for (int r = 1; r < 8; r++) mm = fmaxf(mm, part[r * 32 + t]);
        mm = fmaxf(mm, 1e-30f);
        cmax[t] = mm;
        sw[slot * Dd + n0 + t] = mm * (1.0f / 127.0f);
    }
    __syncthreads();

    // pass 2: quantize into smem staging
    float inv = 127.0f / cmax[tc];
    for (int k = tr; k < Dd; k += 8) {
        float x = W[(size_t)k * Ndim + n0 + tc] * inv;
        int q1 = __float2int_rn(x);
        float r = x - (float)q1;
        int q2 = clampi(__float2int_rn(r * 256.0f), -127, 127);
        q1s[tc * WQ_STRIDE + k] = (char)q1;
        q2s[tc * WQ_STRIDE + k] = (char)q2;
    }
    __syncthreads();

    // writeout: thread t copies 128 B of row r=t>>3, segment seg=t&7
    int r = t >> 3, seg = t & 7;
    size_t dstbase = (size_t)slot * DD2 + (size_t)(n0 + r) * Dd + seg * 128;
    const uint4* s1 = (const uint4*)(q1s + r * WQ_STRIDE + seg * 128);
    const uint4* s2 = (const uint4*)(q2s + r * WQ_STRIDE + seg * 128);
    #pragma unroll
    for (int wds = 0; wds < 8; wds++) {
        ((uint4*)(q1w + dstbase))[wds] = s1[wds];
        ((uint4*)(q2w + dstbase))[wds] = s2[wds];
    }
}

// ---------------- rowwise 2-digit quantization helpers ----------------
__device__ __forceinline__ float block_rowmax(float m, float* red) {
    int t = threadIdx.x;
    #pragma unroll
    for (int o = 16; o > 0; o >>= 1)
        m = fmaxf(m, __shfl_xor_sync(0xffffffff, m, o));
    if ((t & 31) == 0) red[t >> 5] = m;
    __syncthreads();
    if (t < 32) {
        float v = (t < 8) ? red[t] : 0.f;
        #pragma unroll
        for (int o = 4; o > 0; o >>= 1)
            v = fmaxf(v, __shfl_xor_sync(0xffffffff, v, o));
        if (t == 0) red[0] = fmaxf(v, 1e-30f);
    }
    __syncthreads();
    return red[0];
}

__device__ __forceinline__ void quant4_store(float o0, float o1, float o2, float o3,
                                             float inv, int row, int t,
                                             int8_t* q1, int8_t* q2) {
    float x0 = o0 * inv, x1 = o1 * inv, x2 = o2 * inv, x3 = o3 * inv;
    int a0 = __float2int_rn(x0), a1 = __float2int_rn(x1);
    int a2 = __float2int_rn(x2), a3 = __float2int_rn(x3);
    int b0 = clampi(__float2int_rn((x0 - a0) * 256.f), -127, 127);
    int b1 = clampi(__float2int_rn((x1 - a1) * 256.f), -127, 127);
    int b2 = clampi(__float2int_rn((x2 - a2) * 256.f), -127, 127);
    int b3 = clampi(__float2int_rn((x3 - a3) * 256.f), -127, 127);
    char4 c1; c1.x = (char)a0; c1.y = (char)a1; c1.z = (char)a2; c1.w = (char)a3;
    char4 c2; c2.x = (char)b0; c2.y = (char)b1; c2.z = (char)b2; c2.w = (char)b3;
    ((char4*)(q1 + (size_t)row * Dd))[t] = c1;
    ((char4*)(q2 + (size_t)row * Dd))[t] = c2;
}

// ---------------- layernorm + quantize ----------------
__global__ __launch_bounds__(256) void ln_quant_kernel(
        const float* __restrict__ x,
        const float* __restrict__ gamma, const float* __restrict__ beta,
        int8_t* __restrict__ q1, int8_t* __restrict__ q2, float* __restrict__ sa) {
    __shared__ float red_s[8];
    __shared__ float red_q[8];
    __shared__ float red_m[8];
    int row = blockIdx.x;
    int t = threadIdx.x;
    float4 v = ((const float4*)(x + (size_t)row * Dd))[t];
    float s  = v.x + v.y + v.z + v.w;
    float ss = v.x*v.x + v.y*v.y + v.z*v.z + v.w*v.w;
    #pragma unroll
    for (int o = 16; o > 0; o >>= 1) {
        s  += __shfl_xor_sync(0xffffffff, s,  o);
        ss += __shfl_xor_sync(0xffffffff, ss, o);
    }
    if ((t & 31) == 0) { red_s[t >> 5] = s; red_q[t >> 5] = ss; }
    __syncthreads();
    if (t < 32) {
        float a = (t < 8) ? red_s[t] : 0.f;
        float b = (t < 8) ? red_q[t] : 0.f;
        #pragma unroll
        for (int o = 4; o > 0; o >>= 1) {
            a += __shfl_xor_sync(0xffffffff, a, o);
            b += __shfl_xor_sync(0xffffffff, b, o);
        }
        if (t == 0) { red_s[0] = a; red_q[0] = b; }
    }
    __syncthreads();
    float mu  = red_s[0] * (1.0f / Dd);
    float var = red_q[0] * (1.0f / Dd) - mu * mu;
    float inv = rsqrtf(var + 1e-5f);
    float4 g4 = ((const float4*)gamma)[t];
    float4 b4 = ((const float4*)beta)[t];
    float o0 = (v.x - mu) * inv * g4.x + b4.x;
    float o1 = (v.y - mu) * inv * g4.y + b4.y;
    float o2 = (v.z - mu) * inv * g4.z + b4.z;
    float o3 = (v.w - mu) * inv * g4.w + b4.w;
    float m = fmaxf(fmaxf(fabsf(o0), fabsf(o1)), fmaxf(fabsf(o2), fabsf(o3)));
    float rmax = block_rowmax(m, red_m);
    if (t == 0) sa[row] = rmax * (1.0f / 127.0f);
    quant4_store(o0, o1, o2, o3, 127.0f / rmax, row, t, q1, q2);
}

// ---------------- plain rowwise quantization ----------------
__global__ __launch_bounds__(256) void quant_kernel(
        const float* __restrict__ x,
        int8_t* __restrict__ q1, int8_t* __restrict__ q2, float* __restrict__ sa) {
    __shared__ float red_m[8];
    int row = blockIdx.x;
    int t = threadIdx.x;
    float4 v = ((const float4*)(x + (size_t)row * Dd))[t];
    float m = fmaxf(fmaxf(fabsf(v.x), fabsf(v.y)), fmaxf(fabsf(v.z), fabsf(v.w)));
    float rmax = block_rowmax(m, red_m);
    if (t == 0) sa[row] = rmax * (1.0f / 127.0f);
    quant4_store(v.x, v.y, v.z, v.w, 127.0f / rmax, row, t, q1, q2);
}

// ---------------- linear-RNN scan: writes gate fp32 ----------------
__global__ __launch_bounds__(256) void scan_kernel(const float* __restrict__ u,
                                                   const float* __restrict__ v,
                                                   const float* __restrict__ theta,
                                                   float* __restrict__ w) {
    int tid = blockIdx.x * 256 + threadIdx.x;
    int b   = tid / NB;
    int blk = tid % NB;
    float th = theta[blk];
    float c = cosf(th), sn = sinf(th);
    float hx = 0.f, hy = 0.f;
    size_t base = (size_t)b * Ss * (Dd / 2) + blk;
    const float2* up = (const float2*)u + base;
    const float2* vp = (const float2*)v + base;
    float2*       wp = (float2*)w + base;
    for (int s0 = 0; s0 < Ss; s0 += 8) {
        float2 ub[8], vb[8];
        #pragma unroll
        for (int j = 0; j < 8; j++) {
            ub[j] = up[(size_t)(s0 + j) * (Dd / 2)];
            vb[j] = vp[(size_t)(s0 + j) * (Dd / 2)];
        }
        #pragma unroll
        for (int j = 0; j < 8; j++) {
            float nx = c * hx - sn * hy + ub[j].x;
            float ny = sn * hx + c  * hy + ub[j].y;
            hx = nx; hy = ny;
            wp[(size_t)(s0 + j) * (Dd / 2)] = make_float2(hx * vb[j].x, hy * vb[j].y);
        }
    }
}

// ---------------- int8 two-digit GEMM (IMMA m16n8k32, 3-stage) -----------
// C = sA sB (q1a q1b^T + (q1a q2b^T + q2a q1b^T)/256) + bias (+Cin) (relu)
// CTA 128x128xK=1024, 512 threads, 16 warps 4x4, warp tile 32x32, k-slab 32.
#define SROWB 48                       // bytes per smem row (32 data + 16 pad)
#define A_T   (128 * SROWB)            // 6144 B per operand region
#define STAGE (4 * A_T)                // q1a,q2a,q1b,q2b = 24576 B
#define NSTG  3

__device__ __forceinline__ void cp_async16(uint32_t smem, const void* gmem) {
    asm volatile("cp.async.cg.shared.global [%0], [%1], 16;\n" :: "r"(smem), "l"(gmem));
}
__device__ __forceinline__ uint32_t smem_u32(const void* p) {
    uint32_t a;
    asm("{ .reg .u64 t; cvta.to.shared.u64 t, %1; cvt.u32.u64 %0, t; }"
        : "=r"(a) : "l"(p));
    return a;
}
#define LDSM4(r, addr) \
    asm volatile("ldmatrix.sync.aligned.m8n8.x4.shared.b16 {%0,%1,%2,%3}, [%4];" \
                 : "=r"((r)[0]), "=r"((r)[1]), "=r"((r)[2]), "=r"((r)[3]) \
                 : "r"(addr))
#define MMA_S8(ac, a, b0, b1) \
    asm volatile("mma.sync.aligned.m16n8k32.row.col.s32.s8.s8.s32 " \
                 "{%0,%1,%2,%3},{%4,%5,%6,%7},{%8,%9},{%0,%1,%2,%3};\n" \
                 : "+r"((ac)[0]), "+r"((ac)[1]), "+r"((ac)[2]), "+r"((ac)[3]) \
                 : "r"((a)[0]), "r"((a)[1]), "r"((a)[2]), "r"((a)[3]), \
                   "r"(b0), "r"(b1))

__global__ __launch_bounds__(512, 1) void gemm_s8_kernel(
        const int8_t* __restrict__ Aq1, const int8_t* __restrict__ Aq2,
        const float* __restrict__ sA,
        const int8_t* __restrict__ Bq1, const int8_t* __restrict__ Bq2,
        const float* __restrict__ sB,
        const float* __restrict__ bias, const float* __restrict__ Cin,
        float* __restrict__ C, int Ndim, int flags) {
    extern __shared__ __align__(16) char smem[];
    const uint32_t sb = smem_u32(smem);

    int bx = blockIdx.x;            // N tile
    int by = blockIdx.y;            // M tile
    int tid = threadIdx.x;
    int warp = tid >> 5;
    int lane = tid & 31;
    int g = lane >> 2;              // 0..7
    int q = lane & 3;               // 0..3
    int warpM = (warp & 3) * 32;    // 4 warps along M
    int warpN = (warp >> 2) * 32;   // 4 warps along N

    // ldmatrix lane address offsets within a region (bytes)
    int r8  = lane & 7;
    int sub = lane >> 3;            // 0..3
    // A x4 matrices: (r0-7,b0-15),(r8-15,b0-15),(r0-7,b16-31),(r8-15,b16-31)
    uint32_t aoff = (uint32_t)(((sub & 1) * 8 + r8) * SROWB + (sub >> 1) * 16);
    // B x4 matrices: (n0-7,b0-15),(n0-7,b16-31),(n8-15,b0-15),(n8-15,b16-31)
    uint32_t boff = (uint32_t)(((sub >> 1) * 8 + r8) * SROWB + (sub & 1) * 16);

    int accM[2][4][4], accC[2][4][4];
    #pragma unroll
    for (int i = 0; i < 2; i++)
        #pragma unroll
        for (int j = 0; j < 4; j++)
            #pragma unroll
            for (int r = 0; r < 4; r++) { accM[i][j][r] = 0; accC[i][j][r] = 0; }

    const int NIT = Dd / 32;            // 32 k-slabs
    // stage loading: 4 regions x 128 rows x 2 chunks(16B) = 1024 ops, 2/thread
    int reg0 = tid >> 7;                // 0..3 region
    int lrow = tid & 127;               // row in region
    size_t arow = (size_t)(by * 128 + lrow) * Dd;
    size_t brow = (size_t)(bx * 128 + lrow) * Dd;
    const int8_t* srcs[4];
    srcs[0] = Aq1 + arow; srcs[1] = Aq2 + arow;
    srcs[2] = Bq1 + brow; srcs[3] = Bq2 + brow;
    const int8_t* mysrc = srcs[reg0];
    uint32_t mydst = reg0 * A_T + lrow * SROWB;

    auto load_stage = [&](int it, int st) {
        uint32_t stg = sb + st * STAGE + mydst;
        const int8_t* gp = mysrc + it * 32;
        cp_async16(stg,      gp);
        cp_async16(stg + 16, gp + 16);
        asm volatile("cp.async.commit_group;\n");
    };

    load_stage(0, 0);
    load_stage(1, 1);

    for (int it = 0; it < NIT; it++) {
        int st = it % NSTG;
        if (it + 1 < NIT) {
            asm volatile("cp.async.wait_group 1;\n" ::: "memory");
        } else {
            asm volatile("cp.async.wait_group 0;\n" ::: "memory");
        }
        __syncthreads();

        uint32_t stg = sb + st * STAGE;
        uint32_t a1[2][4], a2[2][4], b1[2][4], b2[2][4];
        #pragma unroll
        for (int i = 0; i < 2; i++) {
            LDSM4(a1[i], stg         + (uint32_t)((warpM + i * 16) * SROWB) + aoff);
            LDSM4(a2[i], stg + A_T   + (uint32_t)((warpM + i * 16) * SROWB) + aoff);
        }
        #pragma unroll
        for (int h = 0; h < 2; h++) {
            LDSM4(b1[h], stg + 2 * A_T + (uint32_t)((warpN + h * 16) * SROWB) + boff);
            LDSM4(b2[h], stg + 3 * A_T + (uint32_t)((warpN + h * 16) * SROWB) + boff);
        }
        #pragma unroll
        for (int i = 0; i < 2; i++)
            #pragma unroll
            for (int j = 0; j < 4; j++) {
                int h = j >> 1, jj = (j & 1) * 2;
                MMA_S8(accM[i][j], a1[i], b1[h][jj], b1[h][jj + 1]);
                MMA_S8(accC[i][j], a1[i], b2[h][jj], b2[h][jj + 1]);
                MMA_S8(accC[i][j], a2[i], b1[h][jj], b1[h][jj + 1]);
            }

        __syncthreads();
        if (it + 2 < NIT) load_stage(it + 2, (it + 2) % NSTG);
    }

    // epilogue
    #pragma unroll
    for (int i = 0; i < 2; i++) {
        int r0 = by * 128 + warpM + i * 16 + g;
        int r1 = r0 + 8;
        float sa0 = sA[r0], sa1 = sA[r1];
        #pragma unroll
        for (int j = 0; j < 4; j++) {
            int cc = bx * 128 + warpN + j * 8 + (q << 1);
            float sb0 = sB[cc], sb1 = sB[cc + 1];
            float b0 = bias[cc], b1f = bias[cc + 1];
            float x0 = ((float)accM[i][j][0] + (float)accC[i][j][0] * (1.f/256.f)) * sa0 * sb0 + b0;
            float x1 = ((float)accM[i][j][1] + (float)accC[i][j][1] * (1.f/256.f)) * sa0 * sb1 + b1f;
            float x2 = ((float)accM[i][j][2] + (float)accC[i][j][2] * (1.f/256.f)) * sa1 * sb0 + b0;
            float x3 = ((float)accM[i][j][3] + (float)accC[i][j][3] * (1.f/256.f)) * sa1 * sb1 + b1f;
            if (flags & 1) {
                const float2 ci0 = *(const float2*)(Cin + (size_t)r0 * Ndim + cc);
                const float2 ci1 = *(const float2*)(Cin + (size_t)r1 * Ndim + cc);
                x0 += ci0.x; x1 += ci0.y; x2 += ci1.x; x3 += ci1.y;
            }
            if (flags & 2) {
                x0 = fmaxf(x0, 0.f); x1 = fmaxf(x1, 0.f);
                x2 = fmaxf(x2, 0.f); x3 = fmaxf(x3, 0.f);
            }
            *(float2*)(C + (size_t)r0 * Ndim + cc) = make_float2(x0, x1);
            *(float2*)(C + (size_t)r1 * Ndim + cc) = make_float2(x2, x3);
        }
    }
}

// ---------------- driver ----------------
extern "C" void kernel_launch(void* const* d_in, const int* in_sizes, int n_in,
                              void* d_out, int out_size) {
    const int*   input_x = (const int*)  d_in[0];
    const float* emb     = (const float*)d_in[1];
    const float* theta   = (const float*)d_in[2];
    const float* Wx      = (const float*)d_in[3];
    const float* bx_     = (const float*)d_in[4];
    const float* Wv      = (const float*)d_in[5];
    const float* bv      = (const float*)d_in[6];
    const float* Wh      = (const float*)d_in[7];
    const float* bh      = (const float*)d_in[8];
    const float* ln_g    = (const float*)d_in[9];
    const float* ln_b    = (const float*)d_in[10];
    const float* lnf_g   = (const float*)d_in[11];
    const float* lnf_b   = (const float*)d_in[12];
    const float* Wo1     = (const float*)d_in[13];
    const float* bo1     = (const float*)d_in[14];
    const float* Wo2     = (const float*)d_in[15];
    const float* bo2     = (const float*)d_in[16];

    float *a, *u, *v, *w, *sa, *sw;
    int8_t *qa1, *qa2, *wq1, *wq2;
    cudaGetSymbolAddress((void**)&a,  g_a);
    cudaGetSymbolAddress((void**)&u,  g_u);
    cudaGetSymbolAddress((void**)&v,  g_v);
    cudaGetSymbolAddress((void**)&w,  g_w);
    cudaGetSymbolAddress((void**)&qa1, g_qa1);
    cudaGetSymbolAddress((void**)&qa2, g_qa2);
    cudaGetSymbolAddress((void**)&sa,  g_sa);
    cudaGetSymbolAddress((void**)&wq1, g_wq1);
    cudaGetSymbolAddress((void**)&wq2, g_wq2);
    cudaGetSymbolAddress((void**)&sw,  g_sw);

    const int WQSMEM = 64 * WQ_STRIDE + (8 * 32 + 32) * 4;   // ~67.7 KB
    const int GSMEM  = NSTG * STAGE;                          // 73728
    cudaFuncSetAttribute(wquant_kernel,
                         cudaFuncAttributeMaxDynamicSharedMemorySize, WQSMEM);
    cudaFuncSetAttribute(gemm_s8_kernel,
                         cudaFuncAttributeMaxDynamicSharedMemorySize, GSMEM);

    // weight prep (2 launches so first gemm lands on profiler capture index)
    wquant_kernel<<<dim3(32, 7), 256, WQSMEM>>>(Wx, Wv, Wh, Wo1, Wo2, wq1, wq2, sw, 0);
    wquant_kernel<<<dim3(32, 7), 256, WQSMEM>>>(Wx, Wv, Wh, Wo1, Wo2, wq1, wq2, sw, 7);

    embed_kernel<<<ROWS, 256>>>(input_x, emb, a);

    dim3 grid_DD(Dd / 128, ROWS / 128);   // (8, 256)
    dim3 grid_DV(Vv / 128, ROWS / 128);   // (1, 256)

    for (int l = 0; l < Ll; l++) {
        const int8_t* wxq1 = wq1 + (size_t)(0 + l) * DD2;
        const int8_t* wxq2 = wq2 + (size_t)(0 + l) * DD2;
        const int8_t* wvq1 = wq1 + (size_t)(4 + l) * DD2;
        const int8_t* wvq2 = wq2 + (size_t)(4 + l) * DD2;
        const int8_t* whq1 = wq1 + (size_t)(8 + l) * DD2;
        const int8_t* whq2 = wq2 + (size_t)(8 + l) * DD2;

        ln_quant_kernel<<<ROWS, 256>>>(a, ln_g + (size_t)l * Dd, ln_b + (size_t)l * Dd,
                                       qa1, qa2, sa);
        gemm_s8_kernel<<<grid_DD, 512, GSMEM>>>(qa1, qa2, sa, wxq1, wxq2,
                sw + (size_t)(0 + l) * Dd, bx_ + (size_t)l * Dd, nullptr, u, Dd, 0);
        gemm_s8_kernel<<<grid_DD, 512, GSMEM>>>(qa1, qa2, sa, wvq1, wvq2,
                sw + (size_t)(4 + l) * Dd, bv + (size_t)l * Dd, nullptr, v, Dd, 0);
        scan_kernel<<<(Bb * NB) / 256, 256>>>(u, v, theta + (size_t)l * NB, w);
        quant_kernel<<<ROWS, 256>>>(w, qa1, qa2, sa);
        int flags = (l < Ll - 1) ? 1 : 0;
        gemm_s8_kernel<<<grid_DD, 512, GSMEM>>>(qa1, qa2, sa, whq1, whq2,
                sw + (size_t)(8 + l) * Dd, bh + (size_t)l * Dd, a, a, Dd, flags);
    }

    ln_quant_kernel<<<ROWS, 256>>>(a, lnf_g, lnf_b, qa1, qa2, sa);
    // w = relu(xn @ Wo1 + bo1)
    gemm_s8_kernel<<<grid_DD, 512, GSMEM>>>(qa1, qa2, sa,
            wq1 + (size_t)12 * DD2, wq2 + (size_t)12 * DD2,
            sw + (size_t)12 * Dd, bo1, nullptr, w, Dd, 2);
    quant_kernel<<<ROWS, 256>>>(w, qa1, qa2, sa);
    // out = w @ Wo2 + bo2
    gemm_s8_kernel<<<grid_DV, 512, GSMEM>>>(qa1, qa2, sa,
            wq1 + (size_t)13 * DD2, wq2 + (size_t)13 * DD2,
            sw + (size_t)13 * Dd, bo2, nullptr, (float*)d_out, Vv, 0);
}

// round 8
// speedup vs baseline: 3.5337x; 1.2790x over previous
#include <cuda_runtime.h>
#include <cuda_bf16.h>
#include <cstdint>

// Problem constants
#define Bb 16
#define Ss 2048
#define Dd 1024
#define Vv 128          // vocab
#define Ll 4
#define NB (Dd/2)       // rotation blocks = 512
#define ROWS (Bb*Ss)    // 32768
#define DD2 (Dd*Dd)     // 1048576

// Tiled operand layout: [blk128][kslab32][digit2][row128][k32] bytes.
// One (blk,kslab) cell = 8192 B contiguous (digit0 4096 + digit1 4096).
#define CELL   8192
#define BLKSZ  (32 * CELL)          // 256 KB per 128-row block (full K)
#define WSLOT  (8 * BLKSZ)          // 2 MB per DxD weight slot

// ---------------- scratch (device globals; no allocation allowed) ----------
__device__ float g_a [ROWS*Dd];     // residual stream
__device__ float g_u [ROWS*Dd];     // x@Wx
__device__ float g_v [ROWS*Dd];     // x@Wv
__device__ float g_w [ROWS*Dd];     // gate / relu out (fp32, pre-quant)
__device__ __align__(128) int8_t g_qa[(size_t)ROWS*Dd*2];           // tiled activations
__device__ float  g_sa [ROWS];      // activation row scales
__device__ __align__(128) int8_t g_wq[(size_t)13*WSLOT + 2*BLKSZ];  // tiled weights
__device__ float  g_sw [14*Dd];     // weight row (=output col) scales

__device__ __forceinline__ int clampi(int x, int lo, int hi) {
    return x < lo ? lo : (x > hi ? hi : x);
}
// swizzled byte offset of (row r, k-chunk c16 in {0,1}) within a digit region
__device__ __forceinline__ uint32_t sw_off(int r, int c16) {
    return (uint32_t)(r * 32 + ((c16 ^ ((r >> 2) & 1)) << 4));
}

// ---------------- embedding gather ----------------
__global__ __launch_bounds__(256) void embed_kernel(const int* __restrict__ idx,
                                                    const float* __restrict__ emb,
                                                    float* __restrict__ a) {
    int i = blockIdx.x * 256 + threadIdx.x;
    int row = i >> 8;
    int col = i & 255;
    int tok = idx[row];
    ((float4*)a)[i] = ((const float4*)emb)[tok * 256 + col];
}

// ---------------- weight transpose + 2-digit int8 quant (tiled out) -------
#define WQ_STRIDE 1040
__global__ __launch_bounds__(256) void wquant_kernel(
        const float* __restrict__ Wx, const float* __restrict__ Wv,
        const float* __restrict__ Wh, const float* __restrict__ Wo1,
        const float* __restrict__ Wo2,
        int8_t* __restrict__ wq, float* __restrict__ sw, int slot0) {
    extern __shared__ char wsm[];
    char*  q1s  = wsm;                              // 32*1040
    char*  q2s  = wsm + 32 * WQ_STRIDE;             // 32*1040
    float* part = (float*)(wsm + 64 * WQ_STRIDE);   // 8*32
    float* cmax = part + 8 * 32;                    // 32

    int slot = slot0 + blockIdx.y;
    const float* W;
    int Ndim = Dd;
    if (slot < 4)        W = Wx + (size_t)slot * DD2;
    else if (slot < 8)   W = Wv + (size_t)(slot - 4) * DD2;
    else if (slot < 12)  W = Wh + (size_t)(slot - 8) * DD2;
    else if (slot == 12) W = Wo1;
    else { W = Wo2; Ndim = Vv; }

    int n0 = blockIdx.x * 32;
    if (n0 >= Ndim) return;
    int t = threadIdx.x;
    int tc = t & 31, tr = t >> 5;

    // pass 1: column max
    float m = 0.f;
    for (int k = tr; k < Dd; k += 8)
        m = fmaxf(m, fabsf(W[(size_t)k * Ndim + n0 + tc]));
    part[tr * 32 + tc] = m;
    __syncthreads();
    if (t < 32) {
        float mm = part[t];
        #pragma unroll
        for (int r = 1; r < 8; r++) mm = fmaxf(mm, part[r * 32 + t]);
        mm = fmaxf(mm, 1e-30f);
        cmax[t] = mm;
        sw[slot * Dd + n0 + t] = mm * (1.0f / 127.0f);
    }
    __syncthreads();

    // pass 2: quantize into smem staging
    float inv = 127.0f / cmax[tc];
    for (int k = tr; k < Dd; k += 8) {
        float x = W[(size_t)k * Ndim + n0 + tc] * inv;
        int q1 = __float2int_rn(x);
        float r = x - (float)q1;
        int q2 = clampi(__float2int_rn(r * 256.0f), -127, 127);
        q1s[tc * WQ_STRIDE + k] = (char)q1;
        q2s[tc * WQ_STRIDE + k] = (char)q2;
    }
    __syncthreads();

    // writeout: tiled+swizzled 16B chunks
    int8_t* slotbase = wq + (size_t)slot * WSLOT;
    int nblk = n0 >> 7;
    for (int i = t; i < 32 * 64; i += 256) {
        int row = i >> 6;          // 0..31 local n-row
        int c16 = i & 63;          // 16B chunk index along K
        int nr  = (n0 & 127) + row;
        int ks  = c16 >> 1;
        uint32_t off = sw_off(nr, c16 & 1);
        size_t cell = (size_t)(nblk * 32 + ks) * CELL;
        *(uint4*)(slotbase + cell +        off) = *(const uint4*)(q1s + row * WQ_STRIDE + c16 * 16);
        *(uint4*)(slotbase + cell + 4096 + off) = *(const uint4*)(q2s + row * WQ_STRIDE + c16 * 16);
    }
}

// ---------------- rowwise 2-digit quantization helpers ----------------
__device__ __forceinline__ float block_rowmax(float m, float* red) {
    int t = threadIdx.x;
    #pragma unroll
    for (int o = 16; o > 0; o >>= 1)
        m = fmaxf(m, __shfl_xor_sync(0xffffffff, m, o));
    if ((t & 31) == 0) red[t >> 5] = m;
    __syncthreads();
    if (t < 32) {
        float v = (t < 8) ? red[t] : 0.f;
        #pragma unroll
        for (int o = 4; o > 0; o >>= 1)
            v = fmaxf(v, __shfl_xor_sync(0xffffffff, v, o));
        if (t == 0) red[0] = fmaxf(v, 1e-30f);
    }
    __syncthreads();
    return red[0];
}

__device__ __forceinline__ void quant4_store(float o0, float o1, float o2, float o3,
                                             float inv, int row, int t,
                                             int8_t* __restrict__ qa) {
    float x0 = o0 * inv, x1 = o1 * inv, x2 = o2 * inv, x3 = o3 * inv;
    int a0 = __float2int_rn(x0), a1 = __float2int_rn(x1);
    int a2 = __float2int_rn(x2), a3 = __float2int_rn(x3);
    int b0 = clampi(__float2int_rn((x0 - a0) * 256.f), -127, 127);
    int b1 = clampi(__float2int_rn((x1 - a1) * 256.f), -127, 127);
    int b2 = clampi(__float2int_rn((x2 - a2) * 256.f), -127, 127);
    int b3 = clampi(__float2int_rn((x3 - a3) * 256.f), -127, 127);
    char4 c1; c1.x = (char)a0; c1.y = (char)a1; c1.z = (char)a2; c1.w = (char)a3;
    char4 c2; c2.x = (char)b0; c2.y = (char)b1; c2.z = (char)b2; c2.w = (char)b3;
    int rb = row >> 7, r = row & 127;
    int k  = t * 4;
    int ks = k >> 5, kc = k & 31;
    uint32_t off = sw_off(r, kc >> 4) + (kc & 15);
    size_t cell = (size_t)(rb * 32 + ks) * CELL;
    *(char4*)(qa + cell +        off) = c1;
    *(char4*)(qa + cell + 4096 + off) = c2;
}

// ---------------- layernorm + quantize ----------------
__global__ __launch_bounds__(256) void ln_quant_kernel(
        const float* __restrict__ x,
        const float* __restrict__ gamma, const float* __restrict__ beta,
        int8_t* __restrict__ qa, float* __restrict__ sa) {
    __shared__ float red_s[8];
    __shared__ float red_q[8];
    __shared__ float red_m[8];
    int row = blockIdx.x;
    int t = threadIdx.x;
    float4 v = ((const float4*)(x + (size_t)row * Dd))[t];
    float s  = v.x + v.y + v.z + v.w;
    float ss = v.x*v.x + v.y*v.y + v.z*v.z + v.w*v.w;
    #pragma unroll
    for (int o = 16; o > 0; o >>= 1) {
        s  += __shfl_xor_sync(0xffffffff, s,  o);
        ss += __shfl_xor_sync(0xffffffff, ss, o);
    }
    if ((t & 31) == 0) { red_s[t >> 5] = s; red_q[t >> 5] = ss; }
    __syncthreads();
    if (t < 32) {
        float a = (t < 8) ? red_s[t] : 0.f;
        float b = (t < 8) ? red_q[t] : 0.f;
        #pragma unroll
        for (int o = 4; o > 0; o >>= 1) {
            a += __shfl_xor_sync(0xffffffff, a, o);
            b += __shfl_xor_sync(0xffffffff, b, o);
        }
        if (t == 0) { red_s[0] = a; red_q[0] = b; }
    }
    __syncthreads();
    float mu  = red_s[0] * (1.0f / Dd);
    float var = red_q[0] * (1.0f / Dd) - mu * mu;
    float inv = rsqrtf(var + 1e-5f);
    float4 g4 = ((const float4*)gamma)[t];
    float4 b4 = ((const float4*)beta)[t];
    float o0 = (v.x - mu) * inv * g4.x + b4.x;
    float o1 = (v.y - mu) * inv * g4.y + b4.y;
    float o2 = (v.z - mu) * inv * g4.z + b4.z;
    float o3 = (v.w - mu) * inv * g4.w + b4.w;
    float m = fmaxf(fmaxf(fabsf(o0), fabsf(o1)), fmaxf(fabsf(o2), fabsf(o3)));
    float rmax = block_rowmax(m, red_m);
    if (t == 0) sa[row] = rmax * (1.0f / 127.0f);
    quant4_store(o0, o1, o2, o3, 127.0f / rmax, row, t, qa);
}

// ---------------- plain rowwise quantization ----------------
__global__ __launch_bounds__(256) void quant_kernel(
        const float* __restrict__ x,
        int8_t* __restrict__ qa, float* __restrict__ sa) {
    __shared__ float red_m[8];
    int row = blockIdx.x;
    int t = threadIdx.x;
    float4 v = ((const float4*)(x + (size_t)row * Dd))[t];
    float m = fmaxf(fmaxf(fabsf(v.x), fabsf(v.y)), fmaxf(fabsf(v.z), fabsf(v.w)));
    float rmax = block_rowmax(m, red_m);
    if (t == 0) sa[row] = rmax * (1.0f / 127.0f);
    quant4_store(v.x, v.y, v.z, v.w, 127.0f / rmax, row, t, qa);
}

// ---------------- linear-RNN scan: writes gate fp32 ----------------
__global__ __launch_bounds__(256) void scan_kernel(const float* __restrict__ u,
                                                   const float* __restrict__ v,
                                                   const float* __restrict__ theta,
                                                   float* __restrict__ w) {
    int tid = blockIdx.x * 256 + threadIdx.x;
    int b   = tid / NB;
    int blk = tid % NB;
    float th = theta[blk];
    float c = cosf(th), sn = sinf(th);
    float hx = 0.f, hy = 0.f;
    size_t base = (size_t)b * Ss * (Dd / 2) + blk;
    const float2* up = (const float2*)u + base;
    const float2* vp = (const float2*)v + base;
    float2*       wp = (float2*)w + base;
    for (int s0 = 0; s0 < Ss; s0 += 8) {
        float2 ub[8], vb[8];
        #pragma unroll
        for (int j = 0; j < 8; j++) {
            ub[j] = up[(size_t)(s0 + j) * (Dd / 2)];
            vb[j] = vp[(size_t)(s0 + j) * (Dd / 2)];
        }
        #pragma unroll
        for (int j = 0; j < 8; j++) {
            float nx = c * hx - sn * hy + ub[j].x;
            float ny = sn * hx + c  * hy + ub[j].y;
            hx = nx; hy = ny;
            wp[(size_t)(s0 + j) * (Dd / 2)] = make_float2(hx * vb[j].x, hy * vb[j].y);
        }
    }
}

// ---------------- int8 two-digit GEMM (IMMA + bulk-copy pipeline) --------
// C = sA sB (q1a q1b^T + (q1a q2b^T + q2a q1b^T)/256) + bias (+Cin) (relu)
// CTA 128x128, 512 threads (16 warps 4x4, warp tile 32x32), k-slab 32.
// Operands arrive via cp.async.bulk from tiled gmem: 2 x 8KB per slab.
#define NSTG   4
#define STAGEB (2 * CELL)     // A cell + B cell = 16 KB

__device__ __forceinline__ uint32_t smem_u32(const void* p) {
    uint32_t a;
    asm("{ .reg .u64 t; cvta.to.shared.u64 t, %1; cvt.u32.u64 %0, t; }"
        : "=r"(a) : "l"(p));
    return a;
}
#define MBARRIER_INIT(addr, cnt) \
    asm volatile("mbarrier.init.shared.b64 [%0], %1;" :: "r"((uint32_t)(addr)), "r"((uint32_t)(cnt)) : "memory")
#define MBARRIER_EXPECT_TX(addr, bytes) \
    asm volatile("mbarrier.arrive.expect_tx.shared.b64 _, [%0], %1;" \
                 :: "r"((uint32_t)(addr)), "r"((uint32_t)(bytes)) : "memory")
#define MBARRIER_WAIT_PARITY(addr, par) do { \
    uint32_t _m = (uint32_t)(addr), _p = (uint32_t)(par), _d; \
    asm volatile("{\n\t.reg .pred p;\n\t" \
        "mbarrier.try_wait.parity.acquire.cta.shared::cta.b64 p, [%1], %2;\n\t" \
        "selp.b32 %0, 1, 0, p;\n\t}" : "=r"(_d) : "r"(_m), "r"(_p) : "memory"); \
    if (!_d) { \
        asm volatile("{\n\t.reg .pred P1;\n\tWL_%=:\n\t" \
            "mbarrier.try_wait.parity.acquire.cta.shared::cta.b64 P1, [%0], %1, 0x989680;\n\t" \
            "@P1 bra.uni WD_%=;\n\tbra.uni WL_%=;\n\tWD_%=:\n\t}" \
            :: "r"(_m), "r"(_p) : "memory"); \
    } \
} while(0)
#define BULK_G2S(smem, gmem, bytes, mbar) \
    asm volatile("cp.async.bulk.shared::cluster.global.mbarrier::complete_tx::bytes " \
                 "[%0], [%1], %2, [%3];" \
                 :: "r"((uint32_t)(smem)), "l"(gmem), "r"((uint32_t)(bytes)), \
                    "r"((uint32_t)(mbar)) : "memory")
#define FENCE_ASYNC() \
    asm volatile("fence.proxy.async.shared::cta;" ::: "memory")
#define LDSM4(r, addr) \
    asm volatile("ldmatrix.sync.aligned.m8n8.x4.shared.b16 {%0,%1,%2,%3}, [%4];" \
                 : "=r"((r)[0]), "=r"((r)[1]), "=r"((r)[2]), "=r"((r)[3]) \
                 : "r"(addr))
#define MMA_S8(ac, a, b0, b1) \
    asm volatile("mma.sync.aligned.m16n8k32.row.col.s32.s8.s8.s32 " \
                 "{%0,%1,%2,%3},{%4,%5,%6,%7},{%8,%9},{%0,%1,%2,%3};\n" \
                 : "+r"((ac)[0]), "+r"((ac)[1]), "+r"((ac)[2]), "+r"((ac)[3]) \
                 : "r"((a)[0]), "r"((a)[1]), "r"((a)[2]), "r"((a)[3]), \
                   "r"(b0), "r"(b1))

__global__ __launch_bounds__(512, 1) void gemm_s8_kernel(
        const int8_t* __restrict__ Aq, const float* __restrict__ sA,
        const int8_t* __restrict__ Bq, const float* __restrict__ sB,
        const float* __restrict__ bias, const float* __restrict__ Cin,
        float* __restrict__ C, int Ndim, int flags) {
    extern __shared__ __align__(128) char smem[];
    const uint32_t sb   = smem_u32(smem);
    const uint32_t DATA = sb + 128;            // stages at sb+128

    int bx = blockIdx.x;            // N tile
    int by = blockIdx.y;            // M tile
    int tid = threadIdx.x;
    int warp = tid >> 5;
    int lane = tid & 31;
    int g = lane >> 2;
    int q = lane & 3;
    int warpM = (warp & 3) * 32;
    int warpN = (warp >> 2) * 32;

    // bulk sources: contiguous 256KB per 128-row block
    const int8_t* srcA = Aq + (size_t)by * BLKSZ;
    const int8_t* srcB = Bq + (size_t)bx * BLKSZ;

    // mbarrier init
    if (tid == 0) {
        #pragma unroll
        for (int s = 0; s < NSTG; s++) MBARRIER_INIT(sb + s * 8, 1);
    }
    __syncthreads();
    FENCE_ASYNC();

    // prologue: issue slabs 0..NSTG-2
    if (tid == 0) {
        #pragma unroll
        for (int s = 0; s < NSTG - 1; s++) {
            MBARRIER_EXPECT_TX(sb + s * 8, STAGEB);
            BULK_G2S(DATA + s * STAGEB,        srcA + (size_t)s * CELL, CELL, sb + s * 8);
            BULK_G2S(DATA + s * STAGEB + CELL, srcB + (size_t)s * CELL, CELL, sb + s * 8);
        }
    }

    // ldmatrix lane offsets (constant across stages)
    int r8  = lane & 7;
    int sub = lane >> 3;
    uint32_t aoff[2], boff[2];
    #pragma unroll
    for (int i = 0; i < 2; i++) {
        int mrow = warpM + i * 16 + (sub & 1) * 8 + r8;
        aoff[i] = sw_off(mrow, sub >> 1);
    }
    #pragma unroll
    for (int h = 0; h < 2; h++) {
        int nrow = warpN + h * 16 + (sub >> 1) * 8 + r8;
        boff[h] = CELL + sw_off(nrow, sub & 1);
    }

    int accM[2][4][4], accC[2][4][4];
    #pragma unroll
    for (int i = 0; i < 2; i++)
        #pragma unroll
        for (int j = 0; j < 4; j++)
            #pragma unroll
            for (int r = 0; r < 4; r++) { accM[i][j][r] = 0; accC[i][j][r] = 0; }

    const int NIT = Dd / 32;

    for (int it = 0; it < NIT; it++) {
        int st = it & (NSTG - 1);
        MBARRIER_WAIT_PARITY(sb + st * 8, (it >> 2) & 1);

        // refill: slab it+NSTG-1 into its stage (consumed at it-1, drained by
        // the __syncthreads at the end of iteration it-1)
        if (tid == 0 && it + NSTG - 1 < NIT) {
            int s2 = (it + NSTG - 1) & (NSTG - 1);
            MBARRIER_EXPECT_TX(sb + s2 * 8, STAGEB);
            BULK_G2S(DATA + s2 * STAGEB,        srcA + (size_t)(it + NSTG - 1) * CELL, CELL, sb + s2 * 8);
            BULK_G2S(DATA + s2 * STAGEB + CELL, srcB + (size_t)(it + NSTG - 1) * CELL, CELL, sb + s2 * 8);
        }

        uint32_t stg = DATA + st * STAGEB;
        uint32_t a1[2][4], a2[2][4], b1[2][4], b2[2][4];
        #pragma unroll
        for (int i = 0; i < 2; i++) {
            LDSM4(a1[i], stg        + aoff[i]);
            LDSM4(a2[i], stg + 4096 + aoff[i]);
        }
        #pragma unroll
        for (int h = 0; h < 2; h++) {
            LDSM4(b1[h], stg        + boff[h]);
            LDSM4(b2[h], stg + 4096 + boff[h]);
        }
        #pragma unroll
        for (int i = 0; i < 2; i++)
            #pragma unroll
            for (int j = 0; j < 4; j++) {
                int h = j >> 1, jj = (j & 1) * 2;
                MMA_S8(accM[i][j], a1[i], b1[h][jj], b1[h][jj + 1]);
                MMA_S8(accC[i][j], a1[i], b2[h][jj], b2[h][jj + 1]);
                MMA_S8(accC[i][j], a2[i], b1[h][jj], b1[h][jj + 1]);
            }
        __syncthreads();
    }

    // epilogue
    #pragma unroll
    for (int i = 0; i < 2; i++) {
        int r0 = by * 128 + warpM + i * 16 + g;
        int r1 = r0 + 8;
        float sa0 = sA[r0], sa1 = sA[r1];
        #pragma unroll
        for (int j = 0; j < 4; j++) {
            int cc = bx * 128 + warpN + j * 8 + (q << 1);
            float sb0 = sB[cc], sb1 = sB[cc + 1];
            float b0 = bias[cc], b1f = bias[cc + 1];
            float x0 = ((float)accM[i][j][0] + (float)accC[i][j][0] * (1.f/256.f)) * sa0 * sb0 + b0;
            float x1 = ((float)accM[i][j][1] + (float)accC[i][j][1] * (1.f/256.f)) * sa0 * sb1 + b1f;
            float x2 = ((float)accM[i][j][2] + (float)accC[i][j][2] * (1.f/256.f)) * sa1 * sb0 + b0;
            float x3 = ((float)accM[i][j][3] + (float)accC[i][j][3] * (1.f/256.f)) * sa1 * sb1 + b1f;
            if (flags & 1) {
                const float2 ci0 = *(const float2*)(Cin + (size_t)r0 * Ndim + cc);
                const float2 ci1 = *(const float2*)(Cin + (size_t)r1 * Ndim + cc);
                x0 += ci0.x; x1 += ci0.y; x2 += ci1.x; x3 += ci1.y;
            }
            if (flags & 2) {
                x0 = fmaxf(x0, 0.f); x1 = fmaxf(x1, 0.f);
                x2 = fmaxf(x2, 0.f); x3 = fmaxf(x3, 0.f);
            }
            *(float2*)(C + (size_t)r0 * Ndim + cc) = make_float2(x0, x1);
            *(float2*)(C + (size_t)r1 * Ndim + cc) = make_float2(x2, x3);
        }
    }
}

// ---------------- driver ----------------
extern "C" void kernel_launch(void* const* d_in, const int* in_sizes, int n_in,
                              void* d_out, int out_size) {
    const int*   input_x = (const int*)  d_in[0];
    const float* emb     = (const float*)d_in[1];
    const float* theta   = (const float*)d_in[2];
    const float* Wx      = (const float*)d_in[3];
    const float* bx_     = (const float*)d_in[4];
    const float* Wv      = (const float*)d_in[5];
    const float* bv      = (const float*)d_in[6];
    const float* Wh      = (const float*)d_in[7];
    const float* bh      = (const float*)d_in[8];
    const float* ln_g    = (const float*)d_in[9];
    const float* ln_b    = (const float*)d_in[10];
    const float* lnf_g   = (const float*)d_in[11];
    const float* lnf_b   = (const float*)d_in[12];
    const float* Wo1     = (const float*)d_in[13];
    const float* bo1     = (const float*)d_in[14];
    const float* Wo2     = (const float*)d_in[15];
    const float* bo2     = (const float*)d_in[16];

    float *a, *u, *v, *w, *sa, *sw;
    int8_t *qa, *wq;
    cudaGetSymbolAddress((void**)&a,  g_a);
    cudaGetSymbolAddress((void**)&u,  g_u);
    cudaGetSymbolAddress((void**)&v,  g_v);
    cudaGetSymbolAddress((void**)&w,  g_w);
    cudaGetSymbolAddress((void**)&qa, g_qa);
    cudaGetSymbolAddress((void**)&sa, g_sa);
    cudaGetSymbolAddress((void**)&wq, g_wq);
    cudaGetSymbolAddress((void**)&sw, g_sw);

    const int WQSMEM = 64 * WQ_STRIDE + (8 * 32 + 32) * 4;
    const int GSMEM  = 128 + NSTG * STAGEB;   // 128 + 64K
    cudaFuncSetAttribute(wquant_kernel,
                         cudaFuncAttributeMaxDynamicSharedMemorySize, WQSMEM);
    cudaFuncSetAttribute(gemm_s8_kernel,
                         cudaFuncAttributeMaxDynamicSharedMemorySize, GSMEM);

    wquant_kernel<<<dim3(32, 7), 256, WQSMEM>>>(Wx, Wv, Wh, Wo1, Wo2, wq, sw, 0);
    wquant_kernel<<<dim3(32, 7), 256, WQSMEM>>>(Wx, Wv, Wh, Wo1, Wo2, wq, sw, 7);

    embed_kernel<<<ROWS, 256>>>(input_x, emb, a);

    dim3 grid_DD(Dd / 128, ROWS / 128);   // (8, 256)
    dim3 grid_DV(Vv / 128, ROWS / 128);   // (1, 256)

    for (int l = 0; l < Ll; l++) {
        const int8_t* wx = wq + (size_t)(0 + l) * WSLOT;
        const int8_t* wv = wq + (size_t)(4 + l) * WSLOT;
        const int8_t* wh = wq + (size_t)(8 + l) * WSLOT;

        ln_quant_kernel<<<ROWS, 256>>>(a, ln_g + (size_t)l * Dd, ln_b + (size_t)l * Dd,
                                       qa, sa);
        gemm_s8_kernel<<<grid_DD, 512, GSMEM>>>(qa, sa, wx,
                sw + (size_t)(0 + l) * Dd, bx_ + (size_t)l * Dd, nullptr, u, Dd, 0);
        gemm_s8_kernel<<<grid_DD, 512, GSMEM>>>(qa, sa, wv,
                sw + (size_t)(4 + l) * Dd, bv + (size_t)l * Dd, nullptr, v, Dd, 0);
        scan_kernel<<<(Bb * NB) / 256, 256>>>(u, v, theta + (size_t)l * NB, w);
        quant_kernel<<<ROWS, 256>>>(w, qa, sa);
        int flags = (l < Ll - 1) ? 1 : 0;
        gemm_s8_kernel<<<grid_DD, 512, GSMEM>>>(qa, sa, wh,
                sw + (size_t)(8 + l) * Dd, bh + (size_t)l * Dd, a, a, Dd, flags);
    }

    ln_quant_kernel<<<ROWS, 256>>>(a, lnf_g, lnf_b, qa, sa);
    gemm_s8_kernel<<<grid_DD, 512, GSMEM>>>(qa, sa,
            wq + (size_t)12 * WSLOT, sw + (size_t)12 * Dd, bo1, nullptr, w, Dd, 2);
    quant_kernel<<<ROWS, 256>>>(w, qa, sa);
    gemm_s8_kernel<<<grid_DV, 512, GSMEM>>>(qa, sa,
            wq + (size_t)13 * WSLOT, sw + (size_t)13 * Dd, bo2, nullptr,
            (float*)d_out, Vv, 0);
}

// round 9
// speedup vs baseline: 3.6815x; 1.0418x over previous
#include <cuda_runtime.h>
#include <cuda_bf16.h>
#include <cstdint>

// Problem constants
#define Bb 16
#define Ss 2048
#define Dd 1024
#define Vv 128          // vocab
#define Ll 4
#define NB (Dd/2)       // rotation blocks = 512
#define ROWS (Bb*Ss)    // 32768
#define DD2 (Dd*Dd)     // 1048576

// Tiled operand layout: [blk128][kslab32][digit2][row128][k32] bytes.
#define CELL   8192
#define BLKSZ  (32 * CELL)          // 256 KB per 128-row block (full K)
#define WSLOT  (8 * BLKSZ)          // 2 MB per DxD weight slot

// ---------------- scratch (device globals; no allocation allowed) ----------
__device__ float g_a [ROWS*Dd];     // residual stream
__device__ float g_u [ROWS*Dd];     // x@Wx
__device__ float g_v [ROWS*Dd];     // x@Wv
__device__ float g_w [ROWS*Dd];     // gate / relu out (fp32, pre-quant)
__device__ __align__(128) int8_t g_qa[(size_t)ROWS*Dd*2];           // tiled activations
__device__ float  g_sa [ROWS];      // activation row scales
__device__ __align__(128) int8_t g_wq[(size_t)13*WSLOT + 2*BLKSZ];  // tiled weights
__device__ float  g_sw [14*Dd];     // weight row (=output col) scales

__device__ __forceinline__ int clampi(int x, int lo, int hi) {
    return x < lo ? lo : (x > hi ? hi : x);
}
// swizzled byte offset of (row r, k-chunk c16 in {0,1}) within a digit region
__device__ __forceinline__ uint32_t sw_off(int r, int c16) {
    return (uint32_t)(r * 32 + ((c16 ^ ((r >> 2) & 1)) << 4));
}

// ---------------- embedding gather ----------------
__global__ __launch_bounds__(256) void embed_kernel(const int* __restrict__ idx,
                                                    const float* __restrict__ emb,
                                                    float* __restrict__ a) {
    int i = blockIdx.x * 256 + threadIdx.x;
    int row = i >> 8;
    int col = i & 255;
    int tok = idx[row];
    ((float4*)a)[i] = ((const float4*)emb)[tok * 256 + col];
}

// ---------------- weight transpose + 2-digit int8 quant (tiled out) -------
#define WQ_STRIDE 1040
__global__ __launch_bounds__(256) void wquant_kernel(
        const float* __restrict__ Wx, const float* __restrict__ Wv,
        const float* __restrict__ Wh, const float* __restrict__ Wo1,
        const float* __restrict__ Wo2,
        int8_t* __restrict__ wq, float* __restrict__ sw) {
    extern __shared__ char wsm[];
    char*  q1s  = wsm;                              // 32*1040
    char*  q2s  = wsm + 32 * WQ_STRIDE;             // 32*1040
    float* part = (float*)(wsm + 64 * WQ_STRIDE);   // 8*32
    float* cmax = part + 8 * 32;                    // 32

    int slot = blockIdx.y;
    const float* W;
    int Ndim = Dd;
    if (slot < 4)        W = Wx + (size_t)slot * DD2;
    else if (slot < 8)   W = Wv + (size_t)(slot - 4) * DD2;
    else if (slot < 12)  W = Wh + (size_t)(slot - 8) * DD2;
    else if (slot == 12) W = Wo1;
    else { W = Wo2; Ndim = Vv; }

    int n0 = blockIdx.x * 32;
    if (n0 >= Ndim) return;
    int t = threadIdx.x;
    int tc = t & 31, tr = t >> 5;

    // pass 1: column max
    float m = 0.f;
    for (int k = tr; k < Dd; k += 8)
        m = fmaxf(m, fabsf(W[(size_t)k * Ndim + n0 + tc]));
    part[tr * 32 + tc] = m;
    __syncthreads();
    if (t < 32) {
        float mm = part[t];
        #pragma unroll
        for (int r = 1; r < 8; r++) mm = fmaxf(mm, part[r * 32 + t]);
        mm = fmaxf(mm, 1e-30f);
        cmax[t] = mm;
        sw[slot * Dd + n0 + t] = mm * (1.0f / 127.0f);
    }
    __syncthreads();

    // pass 2: quantize into smem staging
    float inv = 127.0f / cmax[tc];
    for (int k = tr; k < Dd; k += 8) {
        float x = W[(size_t)k * Ndim + n0 + tc] * inv;
        int q1 = __float2int_rn(x);
        float r = x - (float)q1;
        int q2 = clampi(__float2int_rn(r * 256.0f), -127, 127);
        q1s[tc * WQ_STRIDE + k] = (char)q1;
        q2s[tc * WQ_STRIDE + k] = (char)q2;
    }
    __syncthreads();

    // writeout: tiled+swizzled 16B chunks
    int8_t* slotbase = wq + (size_t)slot * WSLOT;
    int nblk = n0 >> 7;
    for (int i = t; i < 32 * 64; i += 256) {
        int row = i >> 6;          // 0..31 local n-row
        int c16 = i & 63;          // 16B chunk index along K
        int nr  = (n0 & 127) + row;
        int ks  = c16 >> 1;
        uint32_t off = sw_off(nr, c16 & 1);
        size_t cell = (size_t)(nblk * 32 + ks) * CELL;
        *(uint4*)(slotbase + cell +        off) = *(const uint4*)(q1s + row * WQ_STRIDE + c16 * 16);
        *(uint4*)(slotbase + cell + 4096 + off) = *(const uint4*)(q2s + row * WQ_STRIDE + c16 * 16);
    }
}

// ---------------- rowwise 2-digit quantization helpers ----------------
__device__ __forceinline__ float block_rowmax(float m, float* red) {
    int t = threadIdx.x;
    #pragma unroll
    for (int o = 16; o > 0; o >>= 1)
        m = fmaxf(m, __shfl_xor_sync(0xffffffff, m, o));
    if ((t & 31) == 0) red[t >> 5] = m;
    __syncthreads();
    if (t < 32) {
        float v = (t < 8) ? red[t] : 0.f;
        #pragma unroll
        for (int o = 4; o > 0; o >>= 1)
            v = fmaxf(v, __shfl_xor_sync(0xffffffff, v, o));
        if (t == 0) red[0] = fmaxf(v, 1e-30f);
    }
    __syncthreads();
    return red[0];
}

__device__ __forceinline__ void quant4_store(float o0, float o1, float o2, float o3,
                                             float inv, int row, int t,
                                             int8_t* __restrict__ qa) {
    float x0 = o0 * inv, x1 = o1 * inv, x2 = o2 * inv, x3 = o3 * inv;
    int a0 = __float2int_rn(x0), a1 = __float2int_rn(x1);
    int a2 = __float2int_rn(x2), a3 = __float2int_rn(x3);
    int b0 = clampi(__float2int_rn((x0 - a0) * 256.f), -127, 127);
    int b1 = clampi(__float2int_rn((x1 - a1) * 256.f), -127, 127);
    int b2 = clampi(__float2int_rn((x2 - a2) * 256.f), -127, 127);
    int b3 = clampi(__float2int_rn((x3 - a3) * 256.f), -127, 127);
    char4 c1; c1.x = (char)a0; c1.y = (char)a1; c1.z = (char)a2; c1.w = (char)a3;
    char4 c2; c2.x = (char)b0; c2.y = (char)b1; c2.z = (char)b2; c2.w = (char)b3;
    int rb = row >> 7, r = row & 127;
    int k  = t * 4;
    int ks = k >> 5, kc = k & 31;
    uint32_t off = sw_off(r, kc >> 4) + (kc & 15);
    size_t cell = (size_t)(rb * 32 + ks) * CELL;
    *(char4*)(qa + cell +        off) = c1;
    *(char4*)(qa + cell + 4096 + off) = c2;
}

// ---------------- layernorm + quantize ----------------
__global__ __launch_bounds__(256) void ln_quant_kernel(
        const float* __restrict__ x,
        const float* __restrict__ gamma, const float* __restrict__ beta,
        int8_t* __restrict__ qa, float* __restrict__ sa) {
    __shared__ float red_s[8];
    __shared__ float red_q[8];
    __shared__ float red_m[8];
    int row = blockIdx.x;
    int t = threadIdx.x;
    float4 v = ((const float4*)(x + (size_t)row * Dd))[t];
    float s  = v.x + v.y + v.z + v.w;
    float ss = v.x*v.x + v.y*v.y + v.z*v.z + v.w*v.w;
    #pragma unroll
    for (int o = 16; o > 0; o >>= 1) {
        s  += __shfl_xor_sync(0xffffffff, s,  o);
        ss += __shfl_xor_sync(0xffffffff, ss, o);
    }
    if ((t & 31) == 0) { red_s[t >> 5] = s; red_q[t >> 5] = ss; }
    __syncthreads();
    if (t < 32) {
        float a = (t < 8) ? red_s[t] : 0.f;
        float b = (t < 8) ? red_q[t] : 0.f;
        #pragma unroll
        for (int o = 4; o > 0; o >>= 1) {
            a += __shfl_xor_sync(0xffffffff, a, o);
            b += __shfl_xor_sync(0xffffffff, b, o);
        }
        if (t == 0) { red_s[0] = a; red_q[0] = b; }
    }
    __syncthreads();
    float mu  = red_s[0] * (1.0f / Dd);
    float var = red_q[0] * (1.0f / Dd) - mu * mu;
    float inv = rsqrtf(var + 1e-5f);
    float4 g4 = ((const float4*)gamma)[t];
    float4 b4 = ((const float4*)beta)[t];
    float o0 = (v.x - mu) * inv * g4.x + b4.x;
    float o1 = (v.y - mu) * inv * g4.y + b4.y;
    float o2 = (v.z - mu) * inv * g4.z + b4.z;
    float o3 = (v.w - mu) * inv * g4.w + b4.w;
    float m = fmaxf(fmaxf(fabsf(o0), fabsf(o1)), fmaxf(fabsf(o2), fabsf(o3)));
    float rmax = block_rowmax(m, red_m);
    if (t == 0) sa[row] = rmax * (1.0f / 127.0f);
    quant4_store(o0, o1, o2, o3, 127.0f / rmax, row, t, qa);
}

// ---------------- plain rowwise quantization ----------------
__global__ __launch_bounds__(256) void quant_kernel(
        const float* __restrict__ x,
        int8_t* __restrict__ qa, float* __restrict__ sa) {
    __shared__ float red_m[8];
    int row = blockIdx.x;
    int t = threadIdx.x;
    float4 v = ((const float4*)(x + (size_t)row * Dd))[t];
    float m = fmaxf(fmaxf(fabsf(v.x), fabsf(v.y)), fmaxf(fabsf(v.z), fabsf(v.w)));
    float rmax = block_rowmax(m, red_m);
    if (t == 0) sa[row] = rmax * (1.0f / 127.0f);
    quant4_store(v.x, v.y, v.z, v.w, 127.0f / rmax, row, t, qa);
}

// ---------------- linear-RNN scan: writes gate fp32 ----------------
__global__ __launch_bounds__(256) void scan_kernel(const float* __restrict__ u,
                                                   const float* __restrict__ v,
                                                   const float* __restrict__ theta,
                                                   float* __restrict__ w) {
    int tid = blockIdx.x * 256 + threadIdx.x;
    int b   = tid / NB;
    int blk = tid % NB;
    float th = theta[blk];
    float c = cosf(th), sn = sinf(th);
    float hx = 0.f, hy = 0.f;
    size_t base = (size_t)b * Ss * (Dd / 2) + blk;
    const float2* up = (const float2*)u + base;
    const float2* vp = (const float2*)v + base;
    float2*       wp = (float2*)w + base;
    for (int s0 = 0; s0 < Ss; s0 += 8) {
        float2 ub[8], vb[8];
        #pragma unroll
        for (int j = 0; j < 8; j++) {
            ub[j] = up[(size_t)(s0 + j) * (Dd / 2)];
            vb[j] = vp[(size_t)(s0 + j) * (Dd / 2)];
        }
        #pragma unroll
        for (int j = 0; j < 8; j++) {
            float nx = c * hx - sn * hy + ub[j].x;
            float ny = sn * hx + c  * hy + ub[j].y;
            hx = nx; hy = ny;
            wp[(size_t)(s0 + j) * (Dd / 2)] = make_float2(hx * vb[j].x, hy * vb[j].y);
        }
    }
}

// ---------------- int8 two-digit GEMM (IMMA + bulk pipeline, mbar-only) ---
// C = sA sB (q1a q1b^T + (q1a q2b^T + q2a q1b^T)/256) + bias (+Cin) (relu)
// CTA 128x128, 512 threads (16 warps 4x4, warp tile 32x32), k-slab 32.
// Producer/consumer mbarriers per stage; NO per-slab __syncthreads.
#define NSTG   5
#define STAGEB (2 * CELL)     // A cell + B cell = 16 KB

__device__ __forceinline__ uint32_t smem_u32(const void* p) {
    uint32_t a;
    asm("{ .reg .u64 t; cvta.to.shared.u64 t, %1; cvt.u32.u64 %0, t; }"
        : "=r"(a) : "l"(p));
    return a;
}
#define MBARRIER_INIT(addr, cnt) \
    asm volatile("mbarrier.init.shared.b64 [%0], %1;" :: "r"((uint32_t)(addr)), "r"((uint32_t)(cnt)) : "memory")
#define MBARRIER_EXPECT_TX(addr, bytes) \
    asm volatile("mbarrier.arrive.expect_tx.shared.b64 _, [%0], %1;" \
                 :: "r"((uint32_t)(addr)), "r"((uint32_t)(bytes)) : "memory")
#define MBARRIER_ARRIVE(addr) \
    asm volatile("mbarrier.arrive.shared.b64 _, [%0];" :: "r"((uint32_t)(addr)) : "memory")
#define MBARRIER_WAIT_PARITY(addr, par) do { \
    uint32_t _m = (uint32_t)(addr), _p = (uint32_t)(par), _d; \
    asm volatile("{\n\t.reg .pred p;\n\t" \
        "mbarrier.try_wait.parity.acquire.cta.shared::cta.b64 p, [%1], %2;\n\t" \
        "selp.b32 %0, 1, 0, p;\n\t}" : "=r"(_d) : "r"(_m), "r"(_p) : "memory"); \
    if (!_d) { \
        asm volatile("{\n\t.reg .pred P1;\n\tWL_%=:\n\t" \
            "mbarrier.try_wait.parity.acquire.cta.shared::cta.b64 P1, [%0], %1, 0x989680;\n\t" \
            "@P1 bra.uni WD_%=;\n\tbra.uni WL_%=;\n\tWD_%=:\n\t}" \
            :: "r"(_m), "r"(_p) : "memory"); \
    } \
} while(0)
#define BULK_G2S(smem, gmem, bytes, mbar) \
    asm volatile("cp.async.bulk.shared::cluster.global.mbarrier::complete_tx::bytes " \
                 "[%0], [%1], %2, [%3];" \
                 :: "r"((uint32_t)(smem)), "l"(gmem), "r"((uint32_t)(bytes)), \
                    "r"((uint32_t)(mbar)) : "memory")
#define FENCE_ASYNC() \
    asm volatile("fence.proxy.async.shared::cta;" ::: "memory")
#define LDSM4(r, addr) \
    asm volatile("ldmatrix.sync.aligned.m8n8.x4.shared.b16 {%0,%1,%2,%3}, [%4];" \
                 : "=r"((r)[0]), "=r"((r)[1]), "=r"((r)[2]), "=r"((r)[3]) \
                 : "r"(addr))
#define MMA_S8(ac, a, b0, b1) \
    asm volatile("mma.sync.aligned.m16n8k32.row.col.s32.s8.s8.s32 " \
                 "{%0,%1,%2,%3},{%4,%5,%6,%7},{%8,%9},{%0,%1,%2,%3};\n" \
                 : "+r"((ac)[0]), "+r"((ac)[1]), "+r"((ac)[2]), "+r"((ac)[3]) \
                 : "r"((a)[0]), "r"((a)[1]), "r"((a)[2]), "r"((a)[3]), \
                   "r"(b0), "r"(b1))

__global__ __launch_bounds__(512, 1) void gemm_s8_kernel(
        const int8_t* __restrict__ Aq, const float* __restrict__ sA,
        const int8_t* __restrict__ Bq, const float* __restrict__ sB,
        const float* __restrict__ bias, const float* __restrict__ Cin,
        float* __restrict__ C, int Ndim, int flags) {
    extern __shared__ __align__(128) char smem[];
    const uint32_t sb    = smem_u32(smem);       // full[s] at sb + s*8
    const uint32_t EMPTY = sb + NSTG * 8;        // empty[s] at EMPTY + s*8
    const uint32_t DATA  = sb + 128;

    int bx = blockIdx.x;            // N tile
    int by = blockIdx.y;            // M tile
    int tid = threadIdx.x;
    int warp = tid >> 5;
    int lane = tid & 31;
    int g = lane >> 2;
    int q = lane & 3;
    int warpM = (warp & 3) * 32;
    int warpN = (warp >> 2) * 32;

    const int8_t* srcA = Aq + (size_t)by * BLKSZ;
    const int8_t* srcB = Bq + (size_t)bx * BLKSZ;

    if (tid == 0) {
        #pragma unroll
        for (int s = 0; s < NSTG; s++) {
            MBARRIER_INIT(sb + s * 8, 1);        // full: tx-based
            MBARRIER_INIT(EMPTY + s * 8, 512);   // empty: all consumers
        }
    }
    __syncthreads();
    FENCE_ASYNC();

    // prologue: issue slabs 0..NSTG-2
    if (tid == 0) {
        #pragma unroll
        for (int s = 0; s < NSTG - 1; s++) {
            MBARRIER_EXPECT_TX(sb + s * 8, STAGEB);
            BULK_G2S(DATA + s * STAGEB,        srcA + (size_t)s * CELL, CELL, sb + s * 8);
            BULK_G2S(DATA + s * STAGEB + CELL, srcB + (size_t)s * CELL, CELL, sb + s * 8);
        }
    }

    // ldmatrix lane offsets (constant across stages)
    int r8  = lane & 7;
    int sub = lane >> 3;
    uint32_t aoff[2], boff[2];
    #pragma unroll
    for (int i = 0; i < 2; i++) {
        int mrow = warpM + i * 16 + (sub & 1) * 8 + r8;
        aoff[i] = sw_off(mrow, sub >> 1);
    }
    #pragma unroll
    for (int h = 0; h < 2; h++) {
        int nrow = warpN + h * 16 + (sub >> 1) * 8 + r8;
        boff[h] = CELL + sw_off(nrow, sub & 1);
    }

    int accM[2][4][4], accC[2][4][4];
    #pragma unroll
    for (int i = 0; i < 2; i++)
        #pragma unroll
        for (int j = 0; j < 4; j++)
            #pragma unroll
            for (int r = 0; r < 4; r++) { accM[i][j][r] = 0; accC[i][j][r] = 0; }

    const int NIT = Dd / 32;   // 32 slabs

    for (int it = 0; it < NIT; it++) {
        int st = it % NSTG;
        MBARRIER_WAIT_PARITY(sb + st * 8, (it / NSTG) & 1);

        // producer: refill slab it+NSTG-1 into stage (it-1)%NSTG after its
        // consumers (slab it-1) have all arrived on empty
        if (tid == 0 && it + NSTG - 1 < NIT) {
            if (it >= 1) {
                int s2 = (it - 1) % NSTG;
                MBARRIER_WAIT_PARITY(EMPTY + s2 * 8, ((it - 1) / NSTG) & 1);
                MBARRIER_EXPECT_TX(sb + s2 * 8, STAGEB);
                BULK_G2S(DATA + s2 * STAGEB,        srcA + (size_t)(it + NSTG - 1) * CELL, CELL, sb + s2 * 8);
                BULK_G2S(DATA + s2 * STAGEB + CELL, srcB + (size_t)(it + NSTG - 1) * CELL, CELL, sb + s2 * 8);
            } else {
                int s2 = NSTG - 1;   // stage NSTG-1 never used yet: no wait
                MBARRIER_EXPECT_TX(sb + s2 * 8, STAGEB);
                BULK_G2S(DATA + s2 * STAGEB,        srcA + (size_t)(NSTG - 1) * CELL, CELL, sb + s2 * 8);
                BULK_G2S(DATA + s2 * STAGEB + CELL, srcB + (size_t)(NSTG - 1) * CELL, CELL, sb + s2 * 8);
            }
        }

        uint32_t stg = DATA + st * STAGEB;
        uint32_t a1[2][4], a2[2][4], b1[2][4], b2[2][4];
        #pragma unroll
        for (int i = 0; i < 2; i++) {
            LDSM4(a1[i], stg        + aoff[i]);
            LDSM4(a2[i], stg + 4096 + aoff[i]);
        }
        #pragma unroll
        for (int h = 0; h < 2; h++) {
            LDSM4(b1[h], stg        + boff[h]);
            LDSM4(b2[h], stg + 4096 + boff[h]);
        }
        #pragma unroll
        for (int i = 0; i < 2; i++)
            #pragma unroll
            for (int j = 0; j < 4; j++) {
                int h = j >> 1, jj = (j & 1) * 2;
                MMA_S8(accM[i][j], a1[i], b1[h][jj], b1[h][jj + 1]);
                MMA_S8(accC[i][j], a1[i], b2[h][jj], b2[h][jj + 1]);
                MMA_S8(accC[i][j], a2[i], b1[h][jj], b1[h][jj + 1]);
            }
        // release stage after MMAs consumed the LDSM registers
        MBARRIER_ARRIVE(EMPTY + st * 8);
    }

    // epilogue
    #pragma unroll
    for (int i = 0; i < 2; i++) {
        int r0 = by * 128 + warpM + i * 16 + g;
        int r1 = r0 + 8;
        float sa0 = sA[r0], sa1 = sA[r1];
        #pragma unroll
        for (int j = 0; j < 4; j++) {
            int cc = bx * 128 + warpN + j * 8 + (q << 1);
            float sb0 = sB[cc], sb1 = sB[cc + 1];
            float b0 = bias[cc], b1f = bias[cc + 1];
            float x0 = ((float)accM[i][j][0] + (float)accC[i][j][0] * (1.f/256.f)) * sa0 * sb0 + b0;
            float x1 = ((float)accM[i][j][1] + (float)accC[i][j][1] * (1.f/256.f)) * sa0 * sb1 + b1f;
            float x2 = ((float)accM[i][j][2] + (float)accC[i][j][2] * (1.f/256.f)) * sa1 * sb0 + b0;
            float x3 = ((float)accM[i][j][3] + (float)accC[i][j][3] * (1.f/256.f)) * sa1 * sb1 + b1f;
            if (flags & 1) {
                const float2 ci0 = *(const float2*)(Cin + (size_t)r0 * Ndim + cc);
                const float2 ci1 = *(const float2*)(Cin + (size_t)r1 * Ndim + cc);
                x0 += ci0.x; x1 += ci0.y; x2 += ci1.x; x3 += ci1.y;
            }
            if (flags & 2) {
                x0 = fmaxf(x0, 0.f); x1 = fmaxf(x1, 0.f);
                x2 = fmaxf(x2, 0.f); x3 = fmaxf(x3, 0.f);
            }
            *(float2*)(C + (size_t)r0 * Ndim + cc) = make_float2(x0, x1);
            *(float2*)(C + (size_t)r1 * Ndim + cc) = make_float2(x2, x3);
        }
    }
}

// ---------------- driver ----------------
extern "C" void kernel_launch(void* const* d_in, const int* in_sizes, int n_in,
                              void* d_out, int out_size) {
    const int*   input_x = (const int*)  d_in[0];
    const float* emb     = (const float*)d_in[1];
    const float* theta   = (const float*)d_in[2];
    const float* Wx      = (const float*)d_in[3];
    const float* bx_     = (const float*)d_in[4];
    const float* Wv      = (const float*)d_in[5];
    const float* bv      = (const float*)d_in[6];
    const float* Wh      = (const float*)d_in[7];
    const float* bh      = (const float*)d_in[8];
    const float* ln_g    = (const float*)d_in[9];
    const float* ln_b    = (const float*)d_in[10];
    const float* lnf_g   = (const float*)d_in[11];
    const float* lnf_b   = (const float*)d_in[12];
    const float* Wo1     = (const float*)d_in[13];
    const float* bo1     = (const float*)d_in[14];
    const float* Wo2     = (const float*)d_in[15];
    const float* bo2     = (const float*)d_in[16];

    float *a, *u, *v, *w, *sa, *sw;
    int8_t *qa, *wq;
    cudaGetSymbolAddress((void**)&a,  g_a);
    cudaGetSymbolAddress((void**)&u,  g_u);
    cudaGetSymbolAddress((void**)&v,  g_v);
    cudaGetSymbolAddress((void**)&w,  g_w);
    cudaGetSymbolAddress((void**)&qa, g_qa);
    cudaGetSymbolAddress((void**)&sa, g_sa);
    cudaGetSymbolAddress((void**)&wq, g_wq);
    cudaGetSymbolAddress((void**)&sw, g_sw);

    const int WQSMEM = 64 * WQ_STRIDE + (8 * 32 + 32) * 4;
    const int GSMEM  = 128 + NSTG * STAGEB;   // 128 + 80K
    cudaFuncSetAttribute(wquant_kernel,
                         cudaFuncAttributeMaxDynamicSharedMemorySize, WQSMEM);
    cudaFuncSetAttribute(gemm_s8_kernel,
                         cudaFuncAttributeMaxDynamicSharedMemorySize, GSMEM);

    // launch 0: all weights in one go (keeps gemm#1 at ncu capture index 3)
    wquant_kernel<<<dim3(32, 14), 256, WQSMEM>>>(Wx, Wv, Wh, Wo1, Wo2, wq, sw);
    // launch 1
    embed_kernel<<<ROWS, 256>>>(input_x, emb, a);

    dim3 grid_DD(Dd / 128, ROWS / 128);   // (8, 256)
    dim3 grid_DV(Vv / 128, ROWS / 128);   // (1, 256)

    for (int l = 0; l < Ll; l++) {
        const int8_t* wx = wq + (size_t)(0 + l) * WSLOT;
        const int8_t* wv = wq + (size_t)(4 + l) * WSLOT;
        const int8_t* wh = wq + (size_t)(8 + l) * WSLOT;

        // launch 2 (l=0): ln_quant ; launch 3 (l=0): first gemm -> profiled
        ln_quant_kernel<<<ROWS, 256>>>(a, ln_g + (size_t)l * Dd, ln_b + (size_t)l * Dd,
                                       qa, sa);
        gemm_s8_kernel<<<grid_DD, 512, GSMEM>>>(qa, sa, wx,
                sw + (size_t)(0 + l) * Dd, bx_ + (size_t)l * Dd, nullptr, u, Dd, 0);
        gemm_s8_kernel<<<grid_DD, 512, GSMEM>>>(qa, sa, wv,
                sw + (size_t)(4 + l) * Dd, bv + (size_t)l * Dd, nullptr, v, Dd, 0);
        scan_kernel<<<(Bb * NB) / 256, 256>>>(u, v, theta + (size_t)l * NB, w);
        quant_kernel<<<ROWS, 256>>>(w, qa, sa);
        int flags = (l < Ll - 1) ? 1 : 0;
        gemm_s8_kernel<<<grid_DD, 512, GSMEM>>>(qa, sa, wh,
                sw + (size_t)(8 + l) * Dd, bh + (size_t)l * Dd, a, a, Dd, flags);
    }

    ln_quant_kernel<<<ROWS, 256>>>(a, lnf_g, lnf_b, qa, sa);
    gemm_s8_kernel<<<grid_DD, 512, GSMEM>>>(qa, sa,
            wq + (size_t)12 * WSLOT, sw + (size_t)12 * Dd, bo1, nullptr, w, Dd, 2);
    quant_kernel<<<ROWS, 256>>>(w, qa, sa);
    gemm_s8_kernel<<<grid_DV, 512, GSMEM>>>(qa, sa,
            wq + (size_t)13 * WSLOT, sw + (size_t)13 * Dd, bo2, nullptr,
            (float*)d_out, Vv, 0);
}

// round 10
// speedup vs baseline: 3.9887x; 1.0835x over previous
#include <cuda_runtime.h>
#include <cuda_bf16.h>
#include <cstdint>

// Problem constants
#define Bb 16
#define Ss 2048
#define Dd 1024
#define Vv 128          // vocab
#define Ll 4
#define NB (Dd/2)       // rotation blocks = 512
#define ROWS (Bb*Ss)    // 32768
#define DD2 (Dd*Dd)     // 1048576

// Tiled operand layout: [blk128][kslab32][digit2][row128][k32] bytes.
#define CELL   8192
#define BLKSZ  (32 * CELL)          // 256 KB per 128-row block (full K)
#define WSLOT  (8 * BLKSZ)          // 2 MB per DxD weight slot

// ---------------- scratch (device globals; no allocation allowed) ----------
__device__ float g_a [ROWS*Dd];          // residual stream
__device__ float g_uv[(size_t)ROWS*2*Dd];// combined u|v  [row][2048]
__device__ float g_w [ROWS*Dd];          // gate / relu out (fp32, pre-quant)
__device__ __align__(128) int8_t g_qa[(size_t)ROWS*Dd*2];           // tiled activations
__device__ float  g_sa [ROWS];           // activation row scales
// slots: 2l=Wx_l, 2l+1=Wv_l (l=0..3), 8+l=Wh_l, 12=Wo1, 13=Wo2
__device__ __align__(128) int8_t g_wq[(size_t)13*WSLOT + 2*BLKSZ];
__device__ float  g_sw [14*Dd];          // weight col scales (slot-major)
__device__ float  g_bc [Ll*2*Dd];        // concat biases [l][bx|bv]

__device__ __forceinline__ int clampi(int x, int lo, int hi) {
    return x < lo ? lo : (x > hi ? hi : x);
}
__device__ __forceinline__ uint32_t sw_off(int r, int c16) {
    return (uint32_t)(r * 32 + ((c16 ^ ((r >> 2) & 1)) << 4));
}

// ---------------- embedding gather ----------------
__global__ __launch_bounds__(256) void embed_kernel(const int* __restrict__ idx,
                                                    const float* __restrict__ emb,
                                                    float* __restrict__ a) {
    int i = blockIdx.x * 256 + threadIdx.x;
    int row = i >> 8;
    int col = i & 255;
    int tok = idx[row];
    ((float4*)a)[i] = ((const float4*)emb)[tok * 256 + col];
}

// ---------------- weight transpose + 2-digit int8 quant (tiled out) -------
#define WQ_STRIDE 1040
__global__ __launch_bounds__(256) void wquant_kernel(
        const float* __restrict__ Wx, const float* __restrict__ Wv,
        const float* __restrict__ Wh, const float* __restrict__ Wo1,
        const float* __restrict__ Wo2,
        const float* __restrict__ bxv, const float* __restrict__ bvv,
        int8_t* __restrict__ wq, float* __restrict__ sw,
        float* __restrict__ bc) {
    extern __shared__ char wsm[];
    char*  q1s  = wsm;
    char*  q2s  = wsm + 32 * WQ_STRIDE;
    float* part = (float*)(wsm + 64 * WQ_STRIDE);
    float* cmax = part + 8 * 32;

    int slot = blockIdx.y;
    const float* W;
    int Ndim = Dd;
    if (slot < 8)        W = ((slot & 1) ? Wv : Wx) + (size_t)(slot >> 1) * DD2;
    else if (slot < 12)  W = Wh + (size_t)(slot - 8) * DD2;
    else if (slot == 12) W = Wo1;
    else { W = Wo2; Ndim = Vv; }

    int t = threadIdx.x;
    // bias concat (once per slot<8, by block x==0)
    if (slot < 8 && blockIdx.x == 0) {
        int l = slot >> 1;
        const float* src = ((slot & 1) ? bvv : bxv) + (size_t)l * Dd;
        float* dst = bc + (size_t)l * 2 * Dd + (slot & 1) * Dd;
        for (int i = t; i < Dd; i += 256) dst[i] = src[i];
    }

    int n0 = blockIdx.x * 32;
    if (n0 >= Ndim) return;
    int tc = t & 31, tr = t >> 5;

    float m = 0.f;
    for (int k = tr; k < Dd; k += 8)
        m = fmaxf(m, fabsf(W[(size_t)k * Ndim + n0 + tc]));
    part[tr * 32 + tc] = m;
    __syncthreads();
    if (t < 32) {
        float mm = part[t];
        #pragma unroll
        for (int r = 1; r < 8; r++) mm = fmaxf(mm, part[r * 32 + t]);
        mm = fmaxf(mm, 1e-30f);
        cmax[t] = mm;
        sw[slot * Dd + n0 + t] = mm * (1.0f / 127.0f);
    }
    __syncthreads();

    float inv = 127.0f / cmax[tc];
    for (int k = tr; k < Dd; k += 8) {
        float x = W[(size_t)k * Ndim + n0 + tc] * inv;
        int q1 = __float2int_rn(x);
        float r = x - (float)q1;
        int q2 = clampi(__float2int_rn(r * 256.0f), -127, 127);
        q1s[tc * WQ_STRIDE + k] = (char)q1;
        q2s[tc * WQ_STRIDE + k] = (char)q2;
    }
    __syncthreads();

    int8_t* slotbase = wq + (size_t)slot * WSLOT;
    int nblk = n0 >> 7;
    for (int i = t; i < 32 * 64; i += 256) {
        int row = i >> 6;
        int c16 = i & 63;
        int nr  = (n0 & 127) + row;
        int ks  = c16 >> 1;
        uint32_t off = sw_off(nr, c16 & 1);
        size_t cell = (size_t)(nblk * 32 + ks) * CELL;
        *(uint4*)(slotbase + cell +        off) = *(const uint4*)(q1s + row * WQ_STRIDE + c16 * 16);
        *(uint4*)(slotbase + cell + 4096 + off) = *(const uint4*)(q2s + row * WQ_STRIDE + c16 * 16);
    }
}

// ---------------- rowwise 2-digit quantization helpers ----------------
__device__ __forceinline__ float block_rowmax(float m, float* red) {
    int t = threadIdx.x;
    #pragma unroll
    for (int o = 16; o > 0; o >>= 1)
        m = fmaxf(m, __shfl_xor_sync(0xffffffff, m, o));
    if ((t & 31) == 0) red[t >> 5] = m;
    __syncthreads();
    if (t < 32) {
        float v = (t < 8) ? red[t] : 0.f;
        #pragma unroll
        for (int o = 4; o > 0; o >>= 1)
            v = fmaxf(v, __shfl_xor_sync(0xffffffff, v, o));
        if (t == 0) red[0] = fmaxf(v, 1e-30f);
    }
    __syncthreads();
    return red[0];
}

__device__ __forceinline__ void quant4_store(float o0, float o1, float o2, float o3,
                                             float inv, int row, int t,
                                             int8_t* __restrict__ qa) {
    float x0 = o0 * inv, x1 = o1 * inv, x2 = o2 * inv, x3 = o3 * inv;
    int a0 = __float2int_rn(x0), a1 = __float2int_rn(x1);
    int a2 = __float2int_rn(x2), a3 = __float2int_rn(x3);
    int b0 = clampi(__float2int_rn((x0 - a0) * 256.f), -127, 127);
    int b1 = clampi(__float2int_rn((x1 - a1) * 256.f), -127, 127);
    int b2 = clampi(__float2int_rn((x2 - a2) * 256.f), -127, 127);
    int b3 = clampi(__float2int_rn((x3 - a3) * 256.f), -127, 127);
    char4 c1; c1.x = (char)a0; c1.y = (char)a1; c1.z = (char)a2; c1.w = (char)a3;
    char4 c2; c2.x = (char)b0; c2.y = (char)b1; c2.z = (char)b2; c2.w = (char)b3;
    int rb = row >> 7, r = row & 127;
    int k  = t * 4;
    int ks = k >> 5, kc = k & 31;
    uint32_t off = sw_off(r, kc >> 4) + (kc & 15);
    size_t cell = (size_t)(rb * 32 + ks) * CELL;
    *(char4*)(qa + cell +        off) = c1;
    *(char4*)(qa + cell + 4096 + off) = c2;
}

// ---------------- layernorm + quantize ----------------
__global__ __launch_bounds__(256) void ln_quant_kernel(
        const float* __restrict__ x,
        const float* __restrict__ gamma, const float* __restrict__ beta,
        int8_t* __restrict__ qa, float* __restrict__ sa) {
    __shared__ float red_s[8];
    __shared__ float red_q[8];
    __shared__ float red_m[8];
    int row = blockIdx.x;
    int t = threadIdx.x;
    float4 v = ((const float4*)(x + (size_t)row * Dd))[t];
    float s  = v.x + v.y + v.z + v.w;
    float ss = v.x*v.x + v.y*v.y + v.z*v.z + v.w*v.w;
    #pragma unroll
    for (int o = 16; o > 0; o >>= 1) {
        s  += __shfl_xor_sync(0xffffffff, s,  o);
        ss += __shfl_xor_sync(0xffffffff, ss, o);
    }
    if ((t & 31) == 0) { red_s[t >> 5] = s; red_q[t >> 5] = ss; }
    __syncthreads();
    if (t < 32) {
        float a = (t < 8) ? red_s[t] : 0.f;
        float b = (t < 8) ? red_q[t] : 0.f;
        #pragma unroll
        for (int o = 4; o > 0; o >>= 1) {
            a += __shfl_xor_sync(0xffffffff, a, o);
            b += __shfl_xor_sync(0xffffffff, b, o);
        }
        if (t == 0) { red_s[0] = a; red_q[0] = b; }
    }
    __syncthreads();
    float mu  = red_s[0] * (1.0f / Dd);
    float var = red_q[0] * (1.0f / Dd) - mu * mu;
    float inv = rsqrtf(var + 1e-5f);
    float4 g4 = ((const float4*)gamma)[t];
    float4 b4 = ((const float4*)beta)[t];
    float o0 = (v.x - mu) * inv * g4.x + b4.x;
    float o1 = (v.y - mu) * inv * g4.y + b4.y;
    float o2 = (v.z - mu) * inv * g4.z + b4.z;
    float o3 = (v.w - mu) * inv * g4.w + b4.w;
    float m = fmaxf(fmaxf(fabsf(o0), fabsf(o1)), fmaxf(fabsf(o2), fabsf(o3)));
    float rmax = block_rowmax(m, red_m);
    if (t == 0) sa[row] = rmax * (1.0f / 127.0f);
    quant4_store(o0, o1, o2, o3, 127.0f / rmax, row, t, qa);
}

// ---------------- plain rowwise quantization ----------------
__global__ __launch_bounds__(256) void quant_kernel(
        const float* __restrict__ x,
        int8_t* __restrict__ qa, float* __restrict__ sa) {
    __shared__ float red_m[8];
    int row = blockIdx.x;
    int t = threadIdx.x;
    float4 v = ((const float4*)(x + (size_t)row * Dd))[t];
    float m = fmaxf(fmaxf(fabsf(v.x), fabsf(v.y)), fmaxf(fabsf(v.z), fabsf(v.w)));
    float rmax = block_rowmax(m, red_m);
    if (t == 0) sa[row] = rmax * (1.0f / 127.0f);
    quant4_store(v.x, v.y, v.z, v.w, 127.0f / rmax, row, t, qa);
}

// ---------------- linear-RNN scan over uv[row][2048]: writes gate fp32 ----
__global__ __launch_bounds__(256) void scan_kernel(const float* __restrict__ uv,
                                                   const float* __restrict__ theta,
                                                   float* __restrict__ w) {
    int tid = blockIdx.x * 256 + threadIdx.x;
    int b   = tid / NB;
    int blk = tid % NB;
    float th = theta[blk];
    float c = cosf(th), sn = sinf(th);
    float hx = 0.f, hy = 0.f;
    const float2* up = (const float2*)uv + (size_t)b * Ss * Dd + blk;   // stride Dd float2
    const float2* vp = up + (Dd / 2);
    float2*       wp = (float2*)w + (size_t)b * Ss * (Dd / 2) + blk;
    for (int s0 = 0; s0 < Ss; s0 += 8) {
        float2 ub[8], vb[8];
        #pragma unroll
        for (int j = 0; j < 8; j++) {
            ub[j] = up[(size_t)(s0 + j) * Dd];
            vb[j] = vp[(size_t)(s0 + j) * Dd];
        }
        #pragma unroll
        for (int j = 0; j < 8; j++) {
            float nx = c * hx - sn * hy + ub[j].x;
            float ny = sn * hx + c  * hy + ub[j].y;
            hx = nx; hy = ny;
            wp[(size_t)(s0 + j) * (Dd / 2)] = make_float2(hx * vb[j].x, hy * vb[j].y);
        }
    }
}

// ---------------- int8 two-digit GEMM (128x64 CTA, 2 CTAs/SM) -------------
// C = sA sB (q1a q1b^T + (q1a q2b^T + q2a q1b^T)/256) + bias (+Cin) (relu)
// 256 threads, 8 warps (4M x 2N), warp tile 32x32, k-slab 32.
#define NSTG   5
#define STAGEB 12288     // A 8KB + B 4KB

__device__ __forceinline__ uint32_t smem_u32(const void* p) {
    uint32_t a;
    asm("{ .reg .u64 t; cvta.to.shared.u64 t, %1; cvt.u32.u64 %0, t; }"
        : "=r"(a) : "l"(p));
    return a;
}
#define MBARRIER_INIT(addr, cnt) \
    asm volatile("mbarrier.init.shared.b64 [%0], %1;" :: "r"((uint32_t)(addr)), "r"((uint32_t)(cnt)) : "memory")
#define MBARRIER_EXPECT_TX(addr, bytes) \
    asm volatile("mbarrier.arrive.expect_tx.shared.b64 _, [%0], %1;" \
                 :: "r"((uint32_t)(addr)), "r"((uint32_t)(bytes)) : "memory")
#define MBARRIER_ARRIVE(addr) \
    asm volatile("mbarrier.arrive.shared.b64 _, [%0];" :: "r"((uint32_t)(addr)) : "memory")
#define MBARRIER_WAIT_PARITY(addr, par) do { \
    uint32_t _m = (uint32_t)(addr), _p = (uint32_t)(par), _d; \
    asm volatile("{\n\t.reg .pred p;\n\t" \
        "mbarrier.try_wait.parity.acquire.cta.shared::cta.b64 p, [%1], %2;\n\t" \
        "selp.b32 %0, 1, 0, p;\n\t}" : "=r"(_d) : "r"(_m), "r"(_p) : "memory"); \
    if (!_d) { \
        asm volatile("{\n\t.reg .pred P1;\n\tWL_%=:\n\t" \
            "mbarrier.try_wait.parity.acquire.cta.shared::cta.b64 P1, [%0], %1, 0x989680;\n\t" \
            "@P1 bra.uni WD_%=;\n\tbra.uni WL_%=;\n\tWD_%=:\n\t}" \
            :: "r"(_m), "r"(_p) : "memory"); \
    } \
} while(0)
#define BULK_G2S(smem, gmem, bytes, mbar) \
    asm volatile("cp.async.bulk.shared::cluster.global.mbarrier::complete_tx::bytes " \
                 "[%0], [%1], %2, [%3];" \
                 :: "r"((uint32_t)(smem)), "l"(gmem), "r"((uint32_t)(bytes)), \
                    "r"((uint32_t)(mbar)) : "memory")
#define FENCE_ASYNC() \
    asm volatile("fence.proxy.async.shared::cta;" ::: "memory")
#define LDSM4(r, addr) \
    asm volatile("ldmatrix.sync.aligned.m8n8.x4.shared.b16 {%0,%1,%2,%3}, [%4];" \
                 : "=r"((r)[0]), "=r"((r)[1]), "=r"((r)[2]), "=r"((r)[3]) \
                 : "r"(addr))
#define MMA_S8(ac, a, b0, b1) \
    asm volatile("mma.sync.aligned.m16n8k32.row.col.s32.s8.s8.s32 " \
                 "{%0,%1,%2,%3},{%4,%5,%6,%7},{%8,%9},{%0,%1,%2,%3};\n" \
                 : "+r"((ac)[0]), "+r"((ac)[1]), "+r"((ac)[2]), "+r"((ac)[3]) \
                 : "r"((a)[0]), "r"((a)[1]), "r"((a)[2]), "r"((a)[3]), \
                   "r"(b0), "r"(b1))

__global__ __launch_bounds__(256, 2) void gemm_s8_kernel(
        const int8_t* __restrict__ Aq, const float* __restrict__ sA,
        const int8_t* __restrict__ Bq, const float* __restrict__ sB,
        const float* __restrict__ bias, const float* __restrict__ Cin,
        float* __restrict__ C, int Ndim, int flags) {
    extern __shared__ __align__(128) char smem[];
    const uint32_t sb    = smem_u32(smem);       // full[s] at sb + s*8
    const uint32_t EMPTY = sb + NSTG * 8;        // empty[s]
    const uint32_t DATA  = sb + 128;

    int bx = blockIdx.x;            // 64-wide N tile
    int by = blockIdx.y;            // 128-high M tile
    int tid = threadIdx.x;
    int warp = tid >> 5;
    int lane = tid & 31;
    int g = lane >> 2;
    int q = lane & 3;
    int warpM = (warp & 3) * 32;    // 4 warps along M=128
    int warpN = (warp >> 2) * 32;   // 2 warps along N=64

    const int8_t* srcA = Aq + (size_t)by * BLKSZ;
    const int8_t* srcB = Bq + (size_t)(bx >> 1) * BLKSZ;
    uint32_t halfoff = (uint32_t)(bx & 1) * 2048;

    if (tid == 0) {
        #pragma unroll
        for (int s = 0; s < NSTG; s++) {
            MBARRIER_INIT(sb + s * 8, 1);
            MBARRIER_INIT(EMPTY + s * 8, 256);
        }
    }
    __syncthreads();
    FENCE_ASYNC();

    if (tid == 0) {
        #pragma unroll
        for (int s = 0; s < NSTG - 1; s++) {
            MBARRIER_EXPECT_TX(sb + s * 8, STAGEB);
            BULK_G2S(DATA + s * STAGEB,         srcA + (size_t)s * CELL, CELL, sb + s * 8);
            BULK_G2S(DATA + s * STAGEB +  8192, srcB + (size_t)s * CELL + halfoff, 2048, sb + s * 8);
            BULK_G2S(DATA + s * STAGEB + 10240, srcB + (size_t)s * CELL + 4096 + halfoff, 2048, sb + s * 8);
        }
    }

    int r8  = lane & 7;
    int sub = lane >> 3;
    uint32_t aoff[2], boff[2];
    #pragma unroll
    for (int i = 0; i < 2; i++) {
        int mrow = warpM + i * 16 + (sub & 1) * 8 + r8;
        aoff[i] = sw_off(mrow, sub >> 1);
    }
    #pragma unroll
    for (int h = 0; h < 2; h++) {
        int nrow = warpN + h * 16 + (sub >> 1) * 8 + r8;   // 0..63 local
        boff[h] = 8192 + sw_off(nrow, sub & 1);
    }

    int accM[2][4][4], accC[2][4][4];
    #pragma unroll
    for (int i = 0; i < 2; i++)
        #pragma unroll
        for (int j = 0; j < 4; j++)
            #pragma unroll
            for (int r = 0; r < 4; r++) { accM[i][j][r] = 0; accC[i][j][r] = 0; }

    const int NIT = Dd / 32;

    for (int it = 0; it < NIT; it++) {
        int st = it % NSTG;
        MBARRIER_WAIT_PARITY(sb + st * 8, (it / NSTG) & 1);

        if (tid == 0 && it + NSTG - 1 < NIT) {
            if (it >= 1) {
                int s2 = (it - 1) % NSTG;
                MBARRIER_WAIT_PARITY(EMPTY + s2 * 8, ((it - 1) / NSTG) & 1);
                MBARRIER_EXPECT_TX(sb + s2 * 8, STAGEB);
                BULK_G2S(DATA + s2 * STAGEB,         srcA + (size_t)(it + NSTG - 1) * CELL, CELL, sb + s2 * 8);
                BULK_G2S(DATA + s2 * STAGEB +  8192, srcB + (size_t)(it + NSTG - 1) * CELL + halfoff, 2048, sb + s2 * 8);
                BULK_G2S(DATA + s2 * STAGEB + 10240, srcB + (size_t)(it + NSTG - 1) * CELL + 4096 + halfoff, 2048, sb + s2 * 8);
            } else {
                int s2 = NSTG - 1;
                MBARRIER_EXPECT_TX(sb + s2 * 8, STAGEB);
                BULK_G2S(DATA + s2 * STAGEB,         srcA + (size_t)(NSTG - 1) * CELL, CELL, sb + s2 * 8);
                BULK_G2S(DATA + s2 * STAGEB +  8192, srcB + (size_t)(NSTG - 1) * CELL + halfoff, 2048, sb + s2 * 8);
                BULK_G2S(DATA + s2 * STAGEB + 10240, srcB + (size_t)(NSTG - 1) * CELL + 4096 + halfoff, 2048, sb + s2 * 8);
            }
        }

        uint32_t stg = DATA + st * STAGEB;
        uint32_t a1[2][4], a2[2][4], b1[2][4], b2[2][4];
        #pragma unroll
        for (int i = 0; i < 2; i++) {
            LDSM4(a1[i], stg        + aoff[i]);
            LDSM4(a2[i], stg + 4096 + aoff[i]);
        }
        #pragma unroll
        for (int h = 0; h < 2; h++) {
            LDSM4(b1[h], stg        + boff[h]);
            LDSM4(b2[h], stg + 2048 + boff[h]);
        }
        #pragma unroll
        for (int i = 0; i < 2; i++)
            #pragma unroll
            for (int j = 0; j < 4; j++) {
                int h = j >> 1, jj = (j & 1) * 2;
                MMA_S8(accM[i][j], a1[i], b1[h][jj], b1[h][jj + 1]);
                MMA_S8(accC[i][j], a1[i], b2[h][jj], b2[h][jj + 1]);
                MMA_S8(accC[i][j], a2[i], b1[h][jj], b1[h][jj + 1]);
            }
        MBARRIER_ARRIVE(EMPTY + st * 8);
    }

    // epilogue
    #pragma unroll
    for (int i = 0; i < 2; i++) {
        int r0 = by * 128 + warpM + i * 16 + g;
        int r1 = r0 + 8;
        float sa0 = sA[r0], sa1 = sA[r1];
        #pragma unroll
        for (int j = 0; j < 4; j++) {
            int cc = bx * 64 + warpN + j * 8 + (q << 1);
            float sb0 = sB[cc], sb1 = sB[cc + 1];
            float b0 = bias[cc], b1f = bias[cc + 1];
            float x0 = ((float)accM[i][j][0] + (float)accC[i][j][0] * (1.f/256.f)) * sa0 * sb0 + b0;
            float x1 = ((float)accM[i][j][1] + (float)accC[i][j][1] * (1.f/256.f)) * sa0 * sb1 + b1f;
            float x2 = ((float)accM[i][j][2] + (float)accC[i][j][2] * (1.f/256.f)) * sa1 * sb0 + b0;
            float x3 = ((float)accM[i][j][3] + (float)accC[i][j][3] * (1.f/256.f)) * sa1 * sb1 + b1f;
            if (flags & 1) {
                const float2 ci0 = *(const float2*)(Cin + (size_t)r0 * Ndim + cc);
                const float2 ci1 = *(const float2*)(Cin + (size_t)r1 * Ndim + cc);
                x0 += ci0.x; x1 += ci0.y; x2 += ci1.x; x3 += ci1.y;
            }
            if (flags & 2) {
                x0 = fmaxf(x0, 0.f); x1 = fmaxf(x1, 0.f);
                x2 = fmaxf(x2, 0.f); x3 = fmaxf(x3, 0.f);
            }
            *(float2*)(C + (size_t)r0 * Ndim + cc) = make_float2(x0, x1);
            *(float2*)(C + (size_t)r1 * Ndim + cc) = make_float2(x2, x3);
        }
    }
}

// ---------------- driver ----------------
extern "C" void kernel_launch(void* const* d_in, const int* in_sizes, int n_in,
                              void* d_out, int out_size) {
    const int*   input_x = (const int*)  d_in[0];
    const float* emb     = (const float*)d_in[1];
    const float* theta   = (const float*)d_in[2];
    const float* Wx      = (const float*)d_in[3];
    const float* bx_     = (const float*)d_in[4];
    const float* Wv      = (const float*)d_in[5];
    const float* bv      = (const float*)d_in[6];
    const float* Wh      = (const float*)d_in[7];
    const float* bh      = (const float*)d_in[8];
    const float* ln_g    = (const float*)d_in[9];
    const float* ln_b    = (const float*)d_in[10];
    const float* lnf_g   = (const float*)d_in[11];
    const float* lnf_b   = (const float*)d_in[12];
    const float* Wo1     = (const float*)d_in[13];
    const float* bo1     = (const float*)d_in[14];
    const float* Wo2     = (const float*)d_in[15];
    const float* bo2     = (const float*)d_in[16];

    float *a, *uv, *w, *sa, *sw, *bc;
    int8_t *qa, *wq;
    cudaGetSymbolAddress((void**)&a,  g_a);
    cudaGetSymbolAddress((void**)&uv, g_uv);
    cudaGetSymbolAddress((void**)&w,  g_w);
    cudaGetSymbolAddress((void**)&qa, g_qa);
    cudaGetSymbolAddress((void**)&sa, g_sa);
    cudaGetSymbolAddress((void**)&wq, g_wq);
    cudaGetSymbolAddress((void**)&sw, g_sw);
    cudaGetSymbolAddress((void**)&bc, g_bc);

    const int WQSMEM = 64 * WQ_STRIDE + (8 * 32 + 32) * 4;
    const int GSMEM  = 128 + NSTG * STAGEB;   // 61568
    cudaFuncSetAttribute(wquant_kernel,
                         cudaFuncAttributeMaxDynamicSharedMemorySize, WQSMEM);
    cudaFuncSetAttribute(gemm_s8_kernel,
                         cudaFuncAttributeMaxDynamicSharedMemorySize, GSMEM);

    // launch 0: weights + bias concat ; launch 1: embed ; launch 2: ln_quant
    // launch 3: first gemm (ncu capture target)
    wquant_kernel<<<dim3(32, 14), 256, WQSMEM>>>(Wx, Wv, Wh, Wo1, Wo2,
                                                 bx_, bv, wq, sw, bc);
    embed_kernel<<<ROWS, 256>>>(input_x, emb, a);

    dim3 grid_XV(2 * Dd / 64, ROWS / 128);   // (32, 256) combined Wx|Wv
    dim3 grid_DD(Dd / 64, ROWS / 128);       // (16, 256)
    dim3 grid_DV(Vv / 64, ROWS / 128);       // (2, 256)

    for (int l = 0; l < Ll; l++) {
        ln_quant_kernel<<<ROWS, 256>>>(a, ln_g + (size_t)l * Dd, ln_b + (size_t)l * Dd,
                                       qa, sa);
        // combined u|v = xn @ [Wx|Wv]
        gemm_s8_kernel<<<grid_XV, 256, GSMEM>>>(qa, sa,
                wq + (size_t)(2 * l) * WSLOT, sw + (size_t)(2 * l) * Dd,
                bc + (size_t)l * 2 * Dd, nullptr, uv, 2 * Dd, 0);
        scan_kernel<<<(Bb * NB) / 256, 256>>>(uv, theta + (size_t)l * NB, w);
        quant_kernel<<<ROWS, 256>>>(w, qa, sa);
        int flags = (l < Ll - 1) ? 1 : 0;
        gemm_s8_kernel<<<grid_DD, 256, GSMEM>>>(qa, sa,
                wq + (size_t)(8 + l) * WSLOT, sw + (size_t)(8 + l) * Dd,
                bh + (size_t)l * Dd, a, a, Dd, flags);
    }

    ln_quant_kernel<<<ROWS, 256>>>(a, lnf_g, lnf_b, qa, sa);
    gemm_s8_kernel<<<grid_DD, 256, GSMEM>>>(qa, sa,
            wq + (size_t)12 * WSLOT, sw + (size_t)12 * Dd, bo1, nullptr, w, Dd, 2);
    quant_kernel<<<ROWS, 256>>>(w, qa, sa);
    gemm_s8_kernel<<<grid_DV, 256, GSMEM>>>(qa, sa,
            wq + (size_t)13 * WSLOT, sw + (size_t)13 * Dd, bo2, nullptr,
            (float*)d_out, Vv, 0);
}